// round 2
// baseline (speedup 1.0000x reference)
#include <cuda_runtime.h>
#include <math.h>

#define NB 4
#define NT 2048
#define ND 1024
#define NH 16
#define NHD 64

// scratch (allocation-free rule: __device__ globals)
__device__ float g_qkv[(size_t)NB * NT * 3 * ND];   // [B,T,3D]
__device__ float g_att[(size_t)NB * NT * ND];       // [B,T,D] attention output

// ---------------------------------------------------------------------------
// SGEMM: C[M,N] = A[M,K] @ B[K,N] + bias[N]   (all row-major, dims % 128 == 0, K % 8 == 0)
// BM=BN=128, BK=8, TM=TN=8, 256 threads
// ---------------------------------------------------------------------------
__global__ __launch_bounds__(256)
void sgemm_bias_kernel(const float* __restrict__ A, const float* __restrict__ B,
                       const float* __restrict__ bias, float* __restrict__ C,
                       int M, int N, int K)
{
    __shared__ float As[8][128];
    __shared__ float Bs[8][128];

    const int tid = threadIdx.x;
    const int tx = tid & 15;          // 0..15
    const int ty = tid >> 4;          // 0..15
    const int rowC = blockIdx.y * 128 + ty * 8;
    const int colC = blockIdx.x * 128 + tx * 8;

    float acc[8][8];
    #pragma unroll
    for (int i = 0; i < 8; i++)
        #pragma unroll
        for (int j = 0; j < 8; j++) acc[i][j] = 0.f;

    const int aRow = tid >> 1;            // 0..127
    const int aCol = (tid & 1) * 4;       // 0 or 4
    const int bRow = tid >> 5;            // 0..7
    const int bCol = (tid & 31) * 4;      // 0..124

    const float* Aptr = A + (size_t)(blockIdx.y * 128) * K;
    const float* Bptr = B + blockIdx.x * 128;

    for (int k0 = 0; k0 < K; k0 += 8) {
        float4 a = *(const float4*)(Aptr + (size_t)aRow * K + k0 + aCol);
        As[aCol + 0][aRow] = a.x;
        As[aCol + 1][aRow] = a.y;
        As[aCol + 2][aRow] = a.z;
        As[aCol + 3][aRow] = a.w;
        float4 bv = *(const float4*)(Bptr + (size_t)(k0 + bRow) * N + bCol);
        *(float4*)&Bs[bRow][bCol] = bv;
        __syncthreads();

        #pragma unroll
        for (int k = 0; k < 8; k++) {
            float ra[8], rb[8];
            #pragma unroll
            for (int i = 0; i < 8; i++) ra[i] = As[k][ty * 8 + i];
            #pragma unroll
            for (int j = 0; j < 8; j++) rb[j] = Bs[k][tx * 8 + j];
            #pragma unroll
            for (int i = 0; i < 8; i++)
                #pragma unroll
                for (int j = 0; j < 8; j++) acc[i][j] += ra[i] * rb[j];
        }
        __syncthreads();
    }

    #pragma unroll
    for (int i = 0; i < 8; i++) {
        #pragma unroll
        for (int j = 0; j < 8; j += 4) {
            float4 o;
            o.x = acc[i][j + 0] + bias[colC + j + 0];
            o.y = acc[i][j + 1] + bias[colC + j + 1];
            o.z = acc[i][j + 2] + bias[colC + j + 2];
            o.w = acc[i][j + 3] + bias[colC + j + 3];
            *(float4*)&C[(size_t)(rowC + i) * N + colC + j] = o;
        }
    }
}

// ---------------------------------------------------------------------------
// Flash attention fp32 with entity bias + causal mask.
// Grid: (T/128, H, B). Block: 128 threads; thread t owns query row q0+t.
// K-tile = 32 keys. Online softmax. P staged through the (reused) bias smem
// tile so no register array is runtime-indexed.
// ---------------------------------------------------------------------------
#define QSTR 65   // Q smem row stride (conflict-free: 65*t mod 32 == t mod 32)
#define BSTR 33   // bias/P smem row stride (odd -> conflict-free)

__global__ __launch_bounds__(128)
void flash_kernel(const float* __restrict__ qkv,
                  const float* __restrict__ ebias,
                  float* __restrict__ out)
{
    extern __shared__ float sm[];
    float* Qs  = sm;                    // 128 * 65
    float* Ks  = Qs + 128 * QSTR;       // 32 * 64
    float* Vs  = Ks + 32 * 64;          // 32 * 64
    float* Bsm = Vs + 32 * 64;          // 128 * 33  (bias, then reused for P)

    const int tid = threadIdx.x;
    const int q0  = blockIdx.x * 128;
    const int h   = blockIdx.y;
    const int b   = blockIdx.z;
    const int q   = q0 + tid;

    const float scale = 0.125f;  // 1/sqrt(64)
    const size_t rowstride = 3 * ND;
    const float* base = qkv + (size_t)b * NT * rowstride + h * NHD;

    // cooperative coalesced Q-tile load
    for (int idx = tid; idx < 128 * NHD; idx += 128) {
        int r = idx >> 6, d = idx & 63;
        Qs[r * QSTR + d] = base[(size_t)(q0 + r) * rowstride + d];
    }

    float O[NHD];
    #pragma unroll
    for (int d = 0; d < NHD; d++) O[d] = 0.f;
    float m = -INFINITY, l = 0.f;

    const int ntiles = (q0 + 128) / 32;

    for (int t = 0; t < ntiles; t++) {
        const int j0 = t * 32;
        __syncthreads();   // previous tile's smem consumers done (also orders Q load)

        // K / V tiles (coalesced)
        for (int idx = tid; idx < 32 * 64; idx += 128) {
            int r = idx >> 6, d = idx & 63;
            size_t off = (size_t)(j0 + r) * rowstride + d;
            Ks[idx] = base[ND + off];
            Vs[idx] = base[2 * ND + off];
        }
        // bias tile 128x32 (coalesced rows)
        for (int idx = tid; idx < 128 * 32; idx += 128) {
            int r = idx >> 5, c = idx & 31;
            Bsm[r * BSTR + c] = ebias[((size_t)b * NT + q0 + r) * NT + j0 + c];
        }
        __syncthreads();

        // S = Q K^T (registers, fully unrolled over j)
        float s[32];
        #pragma unroll
        for (int j = 0; j < 32; j++) s[j] = 0.f;
        #pragma unroll 4
        for (int d = 0; d < 64; d++) {
            float qd = Qs[tid * QSTR + d];
            #pragma unroll
            for (int j = 0; j < 32; j++) s[j] += qd * Ks[j * 64 + d];
        }

        // scale + bias + causal mask, tile max
        float mt = -INFINITY;
        #pragma unroll
        for (int j = 0; j < 32; j++) {
            float v = s[j] * scale + Bsm[tid * BSTR + j];
            v = (j0 + j <= q) ? v : -INFINITY;
            s[j] = v;
            mt = fmaxf(mt, v);
        }

        float mnew = fmaxf(m, mt);
        float corr = __expf(m - mnew);     // m=-inf, mnew finite -> 0 (tile 0)
        float ps = 0.f;
        #pragma unroll
        for (int j = 0; j < 32; j++) {
            float p = __expf(s[j] - mnew); // masked -> exp(-inf) = 0
            Bsm[tid * BSTR + j] = p;       // stage P in smem (own row, no hazard)
            ps += p;
        }
        l = l * corr + ps;
        m = mnew;

        #pragma unroll
        for (int d = 0; d < NHD; d++) O[d] *= corr;

        // O += P @ V  (runtime j loop; P from smem, O stays in regs)
        for (int j = 0; j < 32; j++) {
            float p = Bsm[tid * BSTR + j];
            #pragma unroll
            for (int d = 0; d < NHD; d++) O[d] += p * Vs[j * 64 + d];
        }
    }

    const float inv = 1.f / l;
    float* op = out + ((size_t)b * NT + q) * ND + h * NHD;
    #pragma unroll
    for (int d = 0; d < NHD; d += 4) {
        float4 o;
        o.x = O[d + 0] * inv;
        o.y = O[d + 1] * inv;
        o.z = O[d + 2] * inv;
        o.w = O[d + 3] * inv;
        *(float4*)(op + d) = o;
    }
}

// ---------------------------------------------------------------------------
extern "C" void kernel_launch(void* const* d_in, const int* in_sizes, int n_in,
                              void* d_out, int out_size)
{
    const float* x     = (const float*)d_in[0];   // [B,T,D]
    const float* eb    = (const float*)d_in[1];   // [B,T,T]
    const float* Wqkv  = (const float*)d_in[2];   // [D,3D]
    const float* bqkv  = (const float*)d_in[3];   // [3D]
    const float* Wout  = (const float*)d_in[4];   // [D,D]
    const float* bout  = (const float*)d_in[5];   // [D]
    float* out = (float*)d_out;

    float* qkv = nullptr;
    float* att = nullptr;
    cudaGetSymbolAddress((void**)&qkv, g_qkv);
    cudaGetSymbolAddress((void**)&att, g_att);

    const int M = NB * NT;   // 8192

    // 1) QKV projection: [8192,1024] @ [1024,3072] + b
    {
        dim3 grid(3 * ND / 128, M / 128);
        sgemm_bias_kernel<<<grid, 256>>>(x, Wqkv, bqkv, qkv, M, 3 * ND, ND);
    }

    // 2) flash attention
    {
        const int smem = (128 * QSTR + 2 * 32 * 64 + 128 * BSTR) * sizeof(float); // 66560 B
        cudaFuncSetAttribute(flash_kernel, cudaFuncAttributeMaxDynamicSharedMemorySize, smem);
        dim3 grid(NT / 128, NH, NB);
        flash_kernel<<<grid, 128, smem>>>(qkv, eb, att);
    }

    // 3) output projection: [8192,1024] @ [1024,1024] + b
    {
        dim3 grid(ND / 128, M / 128);
        sgemm_bias_kernel<<<grid, 256>>>(att, Wout, bout, out, M, ND, ND);
    }
}

// round 4
// speedup vs baseline: 1.3257x; 1.3257x over previous
#include <cuda_runtime.h>
#include <cuda_bf16.h>
#include <math.h>
#include <stdint.h>

#define NB 4
#define NT 2048
#define ND 1024
#define NH 16
#define NHD 64

// ---------------------------------------------------------------------------
// scratch (allocation-free rule: __device__ globals)
// ---------------------------------------------------------------------------
__device__ float         g_qkv[(size_t)NB * NT * 3 * ND];        // [B,T,3D] fp32
__device__ __nv_bfloat16 g_x_hi[(size_t)NB * NT * ND];
__device__ __nv_bfloat16 g_x_lo[(size_t)NB * NT * ND];
__device__ __nv_bfloat16 g_wq_hi[(size_t)3 * ND * ND];           // Wqkv^T [3D, D]
__device__ __nv_bfloat16 g_wq_lo[(size_t)3 * ND * ND];
__device__ __nv_bfloat16 g_wo_hi[(size_t)ND * ND];               // Wout^T [D, D]
__device__ __nv_bfloat16 g_wo_lo[(size_t)ND * ND];
__device__ __nv_bfloat16 g_att_hi[(size_t)NB * NT * ND];
__device__ __nv_bfloat16 g_att_lo[(size_t)NB * NT * ND];

// ---------------------------------------------------------------------------
// PTX helpers: ldmatrix / mma.sync bf16 / cp.async  (all baseline sm_80+)
// ---------------------------------------------------------------------------
__device__ __forceinline__ uint32_t smem_u32(const void* p) {
    uint32_t a;
    asm("{ .reg .u64 t; cvta.to.shared.u64 t, %1; cvt.u32.u64 %0, t; }" : "=r"(a) : "l"(p));
    return a;
}
__device__ __forceinline__ void ldsm4(uint32_t* r, uint32_t addr) {
    asm volatile("ldmatrix.sync.aligned.m8n8.x4.shared.b16 {%0,%1,%2,%3}, [%4];"
                 : "=r"(r[0]), "=r"(r[1]), "=r"(r[2]), "=r"(r[3]) : "r"(addr));
}
__device__ __forceinline__ void mma_bf16(float* c, const uint32_t* a, const uint32_t* b) {
    asm volatile(
        "mma.sync.aligned.m16n8k16.row.col.f32.bf16.bf16.f32 "
        "{%0,%1,%2,%3}, {%4,%5,%6,%7}, {%8,%9}, {%0,%1,%2,%3};"
        : "+f"(c[0]), "+f"(c[1]), "+f"(c[2]), "+f"(c[3])
        : "r"(a[0]), "r"(a[1]), "r"(a[2]), "r"(a[3]), "r"(b[0]), "r"(b[1]));
}
__device__ __forceinline__ void cp16(uint32_t smem, const void* g) {
    asm volatile("cp.async.cg.shared.global [%0], [%1], 16;" :: "r"(smem), "l"(g));
}
#define CP_COMMIT() asm volatile("cp.async.commit_group;" ::: "memory")
#define CP_WAIT1()  asm volatile("cp.async.wait_group 1;" ::: "memory")

// ---------------------------------------------------------------------------
// split fp32 -> bf16 hi/lo (elementwise)
// ---------------------------------------------------------------------------
__global__ __launch_bounds__(256)
void split_kernel(const float* __restrict__ src, __nv_bfloat16* __restrict__ hi,
                  __nv_bfloat16* __restrict__ lo, int n)
{
    int i = blockIdx.x * 256 + threadIdx.x;
    if (i < n) {
        float v = src[i];
        __nv_bfloat16 h = __float2bfloat16(v);
        hi[i] = h;
        lo[i] = __float2bfloat16(v - __bfloat162float(h));
    }
}

// ---------------------------------------------------------------------------
// transpose + split: W [K,N] fp32 -> W^T [N,K] bf16 hi/lo
// ---------------------------------------------------------------------------
__global__ __launch_bounds__(256)
void transpose_split_kernel(const float* __restrict__ W, __nv_bfloat16* __restrict__ Thi,
                            __nv_bfloat16* __restrict__ Tlo, int K, int N)
{
    __shared__ float t[32][33];
    const int n0 = blockIdx.x * 32, k0 = blockIdx.y * 32;
    const int tx = threadIdx.x, ty = threadIdx.y;   // 32 x 8
    #pragma unroll
    for (int j = 0; j < 32; j += 8)
        t[ty + j][tx] = W[(size_t)(k0 + ty + j) * N + n0 + tx];
    __syncthreads();
    #pragma unroll
    for (int j = 0; j < 32; j += 8) {
        float v = t[tx][ty + j];
        __nv_bfloat16 h = __float2bfloat16(v);
        size_t o = (size_t)(n0 + ty + j) * K + k0 + tx;
        Thi[o] = h;
        Tlo[o] = __float2bfloat16(v - __bfloat162float(h));
    }
}

// ---------------------------------------------------------------------------
// mma.sync bf16x3 GEMM: C[M,N] = A[M,K] @ B[N,K]^T + bias[N], fp32 out.
// 256 threads (8 warps, 4x2), tile 128x128, BK=32, 3-stage cp.async pipeline.
// smem per stage: Ahi|Alo|Bhi|Blo, each 128 rows x stride 40 bf16 (80B).
// ---------------------------------------------------------------------------
#define STG_BYTES 40960           // 4 * 128 * 80
#define T_AHI 0
#define T_ALO 10240
#define T_BHI 20480
#define T_BLO 30720

__global__ __launch_bounds__(256)
void gemm_bf16x3(const __nv_bfloat16* __restrict__ Ahi, const __nv_bfloat16* __restrict__ Alo,
                 const __nv_bfloat16* __restrict__ Bhi, const __nv_bfloat16* __restrict__ Blo,
                 const float* __restrict__ bias, float* __restrict__ C,
                 int M, int N, int K)
{
    extern __shared__ char dynsm[];
    const uint32_t sb0 = smem_u32(dynsm);

    const int tid = threadIdx.x;
    const int wid = tid >> 5;
    const int l   = tid & 31;
    const int wm  = wid >> 1;           // 0..3  -> 32-row band
    const int wn  = wid & 1;            // 0..1  -> 64-col band
    const size_t m0 = (size_t)blockIdx.y * 128;
    const size_t n0 = (size_t)blockIdx.x * 128;

    // global-load mapping: per tile 128 rows x 4 x 16B chunks; thread does 2
    const int r1 = tid >> 2;            // 0..63
    const int r2 = r1 + 64;
    const int cc = (tid & 3);           // 16B chunk in row
    const uint32_t sm_off1 = (uint32_t)r1 * 80 + cc * 16;
    const uint32_t sm_off2 = (uint32_t)r2 * 80 + cc * 16;

    const int nchunks = K >> 5;

    auto issue_stage = [&](int c, int buf) {
        const int kc = c << 5;
        const uint32_t sb = sb0 + buf * STG_BYTES;
        const __nv_bfloat16* a1 = Ahi + (m0 + r1) * K + kc + cc * 8;
        const __nv_bfloat16* a2 = Ahi + (m0 + r2) * K + kc + cc * 8;
        cp16(sb + T_AHI + sm_off1, a1);
        cp16(sb + T_AHI + sm_off2, a2);
        const __nv_bfloat16* al1 = Alo + (m0 + r1) * K + kc + cc * 8;
        const __nv_bfloat16* al2 = Alo + (m0 + r2) * K + kc + cc * 8;
        cp16(sb + T_ALO + sm_off1, al1);
        cp16(sb + T_ALO + sm_off2, al2);
        const __nv_bfloat16* b1 = Bhi + (n0 + r1) * K + kc + cc * 8;
        const __nv_bfloat16* b2 = Bhi + (n0 + r2) * K + kc + cc * 8;
        cp16(sb + T_BHI + sm_off1, b1);
        cp16(sb + T_BHI + sm_off2, b2);
        const __nv_bfloat16* bl1 = Blo + (n0 + r1) * K + kc + cc * 8;
        const __nv_bfloat16* bl2 = Blo + (n0 + r2) * K + kc + cc * 8;
        cp16(sb + T_BLO + sm_off1, bl1);
        cp16(sb + T_BLO + sm_off2, bl2);
        CP_COMMIT();
    };

    // fragment address lane components
    const int aRow = (l & 7) + ((l >> 3) & 1) * 8;     // 0..15
    const int aCol8 = (l >> 4) * 8;                    // 0 / 8
    const int bRow = (l & 7) + ((l >> 4) & 1) * 8;     // 0..15
    const int bCol8 = ((l >> 3) & 1) * 8;              // 0 / 8

    float acc[2][8][4];
    #pragma unroll
    for (int mt = 0; mt < 2; mt++)
        #pragma unroll
        for (int nt = 0; nt < 8; nt++)
            #pragma unroll
            for (int k = 0; k < 4; k++) acc[mt][nt][k] = 0.f;

    issue_stage(0, 0);
    issue_stage(1, 1);

    for (int c = 0; c < nchunks; c++) {
        CP_WAIT1();
        __syncthreads();
        if (c + 2 < nchunks) issue_stage(c + 2, (c + 2) % 3);

        const uint32_t sb = sb0 + (c % 3) * STG_BYTES;
        const uint32_t aBase = sb + (uint32_t)(wm * 32 + aRow) * 80 + aCol8 * 2;
        const uint32_t bBase = sb + (uint32_t)(wn * 64 + bRow) * 80 + bCol8 * 2;

        #pragma unroll
        for (int ks = 0; ks < 2; ks++) {
            uint32_t ah[2][4], al4[2][4], bh[4][4], bl4[4][4];
            #pragma unroll
            for (int mt = 0; mt < 2; mt++) {
                ldsm4(ah[mt],  aBase + T_AHI + mt * (16 * 80) + ks * 32);
                ldsm4(al4[mt], aBase + T_ALO + mt * (16 * 80) + ks * 32);
            }
            #pragma unroll
            for (int np = 0; np < 4; np++) {
                ldsm4(bh[np],  bBase + T_BHI + np * (16 * 80) + ks * 32);
                ldsm4(bl4[np], bBase + T_BLO + np * (16 * 80) + ks * 32);
            }
            #pragma unroll
            for (int mt = 0; mt < 2; mt++)
                #pragma unroll
                for (int nt = 0; nt < 8; nt++) {
                    const int np = nt >> 1, sub = nt & 1;
                    mma_bf16(acc[mt][nt], ah[mt],  &bh[np][sub * 2]);
                    mma_bf16(acc[mt][nt], ah[mt],  &bl4[np][sub * 2]);
                    mma_bf16(acc[mt][nt], al4[mt], &bh[np][sub * 2]);
                }
        }
        __syncthreads();
    }

    // epilogue: fragments -> gmem with bias
    #pragma unroll
    for (int mt = 0; mt < 2; mt++) {
        const size_t row0 = m0 + wm * 32 + mt * 16 + (l >> 2);
        #pragma unroll
        for (int nt = 0; nt < 8; nt++) {
            const size_t col = n0 + wn * 64 + nt * 8 + (l & 3) * 2;
            const float b0 = bias[col], b1 = bias[col + 1];
            float2 v0 = { acc[mt][nt][0] + b0, acc[mt][nt][1] + b1 };
            float2 v1 = { acc[mt][nt][2] + b0, acc[mt][nt][3] + b1 };
            *reinterpret_cast<float2*>(&C[row0 * N + col]) = v0;
            *reinterpret_cast<float2*>(&C[(row0 + 8) * N + col]) = v1;
        }
    }
}

// ---------------------------------------------------------------------------
// Flash attention fp32 with entity bias + causal mask (unchanged from R2).
// Outputs bf16 hi/lo for the tensor-core out-projection.
// ---------------------------------------------------------------------------
#define QSTR 65
#define BSTR 33

__global__ __launch_bounds__(128)
void flash_kernel(const float* __restrict__ qkv,
                  const float* __restrict__ ebias,
                  __nv_bfloat16* __restrict__ out_hi,
                  __nv_bfloat16* __restrict__ out_lo)
{
    extern __shared__ float sm[];
    float* Qs  = sm;                    // 128 * 65
    float* Ks  = Qs + 128 * QSTR;       // 32 * 64
    float* Vs  = Ks + 32 * 64;          // 32 * 64
    float* Bsm = Vs + 32 * 64;          // 128 * 33

    const int tid = threadIdx.x;
    const int q0  = blockIdx.x * 128;
    const int h   = blockIdx.y;
    const int b   = blockIdx.z;
    const int q   = q0 + tid;

    const float scale = 0.125f;
    const size_t rowstride = 3 * ND;
    const float* base = qkv + (size_t)b * NT * rowstride + h * NHD;

    for (int idx = tid; idx < 128 * NHD; idx += 128) {
        int r = idx >> 6, d = idx & 63;
        Qs[r * QSTR + d] = base[(size_t)(q0 + r) * rowstride + d];
    }

    float O[NHD];
    #pragma unroll
    for (int d = 0; d < NHD; d++) O[d] = 0.f;
    float m = -INFINITY, lsum = 0.f;

    const int ntiles = (q0 + 128) / 32;

    for (int t = 0; t < ntiles; t++) {
        const int j0 = t * 32;
        __syncthreads();

        for (int idx = tid; idx < 32 * 64; idx += 128) {
            int r = idx >> 6, d = idx & 63;
            size_t off = (size_t)(j0 + r) * rowstride + d;
            Ks[idx] = base[ND + off];
            Vs[idx] = base[2 * ND + off];
        }
        for (int idx = tid; idx < 128 * 32; idx += 128) {
            int r = idx >> 5, c2 = idx & 31;
            Bsm[r * BSTR + c2] = ebias[((size_t)b * NT + q0 + r) * NT + j0 + c2];
        }
        __syncthreads();

        float s[32];
        #pragma unroll
        for (int j = 0; j < 32; j++) s[j] = 0.f;
        #pragma unroll 4
        for (int d = 0; d < 64; d++) {
            float qd = Qs[tid * QSTR + d];
            #pragma unroll
            for (int j = 0; j < 32; j++) s[j] += qd * Ks[j * 64 + d];
        }

        float mt = -INFINITY;
        #pragma unroll
        for (int j = 0; j < 32; j++) {
            float v = s[j] * scale + Bsm[tid * BSTR + j];
            v = (j0 + j <= q) ? v : -INFINITY;
            s[j] = v;
            mt = fmaxf(mt, v);
        }

        float mnew = fmaxf(m, mt);
        float corr = __expf(m - mnew);
        float ps = 0.f;
        #pragma unroll
        for (int j = 0; j < 32; j++) {
            float p = __expf(s[j] - mnew);
            Bsm[tid * BSTR + j] = p;
            ps += p;
        }
        lsum = lsum * corr + ps;
        m = mnew;

        #pragma unroll
        for (int d = 0; d < NHD; d++) O[d] *= corr;

        for (int j = 0; j < 32; j++) {
            float p = Bsm[tid * BSTR + j];
            #pragma unroll
            for (int d = 0; d < NHD; d++) O[d] += p * Vs[j * 64 + d];
        }
    }

    const float inv = 1.f / lsum;
    const size_t off = ((size_t)b * NT + q) * ND + h * NHD;
    #pragma unroll
    for (int d = 0; d < NHD; d += 2) {
        float o0 = O[d] * inv, o1 = O[d + 1] * inv;
        __nv_bfloat16 h0 = __float2bfloat16(o0);
        __nv_bfloat16 h1 = __float2bfloat16(o1);
        __nv_bfloat162 hv; hv.x = h0; hv.y = h1;
        __nv_bfloat162 lv;
        lv.x = __float2bfloat16(o0 - __bfloat162float(h0));
        lv.y = __float2bfloat16(o1 - __bfloat162float(h1));
        *reinterpret_cast<__nv_bfloat162*>(out_hi + off + d) = hv;
        *reinterpret_cast<__nv_bfloat162*>(out_lo + off + d) = lv;
    }
}

// ---------------------------------------------------------------------------
extern "C" void kernel_launch(void* const* d_in, const int* in_sizes, int n_in,
                              void* d_out, int out_size)
{
    const float* x     = (const float*)d_in[0];   // [B,T,D]
    const float* eb    = (const float*)d_in[1];   // [B,T,T]
    const float* Wqkv  = (const float*)d_in[2];   // [D,3D]
    const float* bqkv  = (const float*)d_in[3];   // [3D]
    const float* Wout  = (const float*)d_in[4];   // [D,D]
    const float* bout  = (const float*)d_in[5];   // [D]
    float* out = (float*)d_out;

    float *qkv = nullptr;
    __nv_bfloat16 *xhi, *xlo, *wqhi, *wqlo, *wohi, *wolo, *athi, *atlo;
    cudaGetSymbolAddress((void**)&qkv,  g_qkv);
    cudaGetSymbolAddress((void**)&xhi,  g_x_hi);
    cudaGetSymbolAddress((void**)&xlo,  g_x_lo);
    cudaGetSymbolAddress((void**)&wqhi, g_wq_hi);
    cudaGetSymbolAddress((void**)&wqlo, g_wq_lo);
    cudaGetSymbolAddress((void**)&wohi, g_wo_hi);
    cudaGetSymbolAddress((void**)&wolo, g_wo_lo);
    cudaGetSymbolAddress((void**)&athi, g_att_hi);
    cudaGetSymbolAddress((void**)&atlo, g_att_lo);

    const int M = NB * NT;   // 8192

    // 0) precision splits / weight transposes
    split_kernel<<<(M * ND + 255) / 256, 256>>>(x, xhi, xlo, M * ND);
    {
        dim3 blk(32, 8);
        transpose_split_kernel<<<dim3(3 * ND / 32, ND / 32), blk>>>(Wqkv, wqhi, wqlo, ND, 3 * ND);
        transpose_split_kernel<<<dim3(ND / 32, ND / 32), blk>>>(Wout, wohi, wolo, ND, ND);
    }

    const int gemm_smem = 3 * STG_BYTES;   // 122880
    cudaFuncSetAttribute(gemm_bf16x3, cudaFuncAttributeMaxDynamicSharedMemorySize, gemm_smem);

    // 1) QKV projection (tensor cores): [8192,1024] @ [1024,3072] + b
    gemm_bf16x3<<<dim3(3 * ND / 128, M / 128), 256, gemm_smem>>>(
        xhi, xlo, wqhi, wqlo, bqkv, qkv, M, 3 * ND, ND);

    // 2) flash attention (fp32 SIMT)
    {
        const int smem = (128 * QSTR + 2 * 32 * 64 + 128 * BSTR) * sizeof(float);
        cudaFuncSetAttribute(flash_kernel, cudaFuncAttributeMaxDynamicSharedMemorySize, smem);
        flash_kernel<<<dim3(NT / 128, NH, NB), 128, smem>>>(qkv, eb, athi, atlo);
    }

    // 3) output projection (tensor cores): [8192,1024] @ [1024,1024] + b
    gemm_bf16x3<<<dim3(ND / 128, M / 128), 256, gemm_smem>>>(
        athi, atlo, wohi, wolo, bout, out, M, ND, ND);
}

// round 5
// speedup vs baseline: 1.9255x; 1.4524x over previous
#include <cuda_runtime.h>
#include <cuda_bf16.h>
#include <math.h>
#include <stdint.h>

#define NB 4
#define NT 2048
#define ND 1024
#define NH 16
#define NHD 64

// ---------------------------------------------------------------------------
// scratch (allocation-free rule: __device__ globals)
// ---------------------------------------------------------------------------
__device__ __align__(256) float         g_qkv[(size_t)NB * NT * 3 * ND];   // [B,T,3D] fp32
__device__ __align__(256) __nv_bfloat16 g_x_hi[(size_t)NB * NT * ND];
__device__ __align__(256) __nv_bfloat16 g_x_lo[(size_t)NB * NT * ND];
__device__ __align__(256) __nv_bfloat16 g_wq_hi[(size_t)3 * ND * ND];      // Wqkv^T [3D, D]
__device__ __align__(256) __nv_bfloat16 g_wq_lo[(size_t)3 * ND * ND];
__device__ __align__(256) __nv_bfloat16 g_wo_hi[(size_t)ND * ND];          // Wout^T [D, D]
__device__ __align__(256) __nv_bfloat16 g_wo_lo[(size_t)ND * ND];
__device__ __align__(256) __nv_bfloat16 g_att_hi[(size_t)NB * NT * ND];
__device__ __align__(256) __nv_bfloat16 g_att_lo[(size_t)NB * NT * ND];
// per-head split q/k/v: [B,H,T,64] bf16
__device__ __align__(256) __nv_bfloat16 g_q_hi[(size_t)NB * NH * NT * NHD];
__device__ __align__(256) __nv_bfloat16 g_q_lo[(size_t)NB * NH * NT * NHD];
__device__ __align__(256) __nv_bfloat16 g_k_hi[(size_t)NB * NH * NT * NHD];
__device__ __align__(256) __nv_bfloat16 g_k_lo[(size_t)NB * NH * NT * NHD];
__device__ __align__(256) __nv_bfloat16 g_v_hi[(size_t)NB * NH * NT * NHD];
__device__ __align__(256) __nv_bfloat16 g_v_lo[(size_t)NB * NH * NT * NHD];

// ---------------------------------------------------------------------------
// PTX helpers (all baseline sm_80+)
// ---------------------------------------------------------------------------
__device__ __forceinline__ uint32_t smem_u32(const void* p) {
    uint32_t a;
    asm("{ .reg .u64 t; cvta.to.shared.u64 t, %1; cvt.u32.u64 %0, t; }" : "=r"(a) : "l"(p));
    return a;
}
__device__ __forceinline__ void ldsm4(uint32_t* r, uint32_t addr) {
    asm volatile("ldmatrix.sync.aligned.m8n8.x4.shared.b16 {%0,%1,%2,%3}, [%4];"
                 : "=r"(r[0]), "=r"(r[1]), "=r"(r[2]), "=r"(r[3]) : "r"(addr));
}
__device__ __forceinline__ void ldsm4t(uint32_t* r, uint32_t addr) {
    asm volatile("ldmatrix.sync.aligned.m8n8.x4.trans.shared.b16 {%0,%1,%2,%3}, [%4];"
                 : "=r"(r[0]), "=r"(r[1]), "=r"(r[2]), "=r"(r[3]) : "r"(addr));
}
__device__ __forceinline__ void mma_bf16(float* c, const uint32_t* a, const uint32_t* b) {
    asm volatile(
        "mma.sync.aligned.m16n8k16.row.col.f32.bf16.bf16.f32 "
        "{%0,%1,%2,%3}, {%4,%5,%6,%7}, {%8,%9}, {%0,%1,%2,%3};"
        : "+f"(c[0]), "+f"(c[1]), "+f"(c[2]), "+f"(c[3])
        : "r"(a[0]), "r"(a[1]), "r"(a[2]), "r"(a[3]), "r"(b[0]), "r"(b[1]));
}
__device__ __forceinline__ void cp16(uint32_t smem, const void* g) {
    asm volatile("cp.async.cg.shared.global [%0], [%1], 16;" :: "r"(smem), "l"(g));
}
#define CP_COMMIT() asm volatile("cp.async.commit_group;" ::: "memory")
#define CP_WAIT1()  asm volatile("cp.async.wait_group 1;" ::: "memory")
#define CP_WAIT0()  asm volatile("cp.async.wait_group 0;" ::: "memory")
#define CP_WAIT2()  asm volatile("cp.async.wait_group 2;" ::: "memory")

__device__ __forceinline__ uint32_t packbf(float a, float b) {
    __nv_bfloat162 t = __float22bfloat162_rn(make_float2(a, b));
    return *reinterpret_cast<uint32_t*>(&t);
}
__device__ __forceinline__ uint32_t packlo(float a, float b, uint32_t hi) {
    __nv_bfloat162 h = *reinterpret_cast<__nv_bfloat162*>(&hi);
    float2 hf = __bfloat1622float2(h);
    return packbf(a - hf.x, b - hf.y);
}

// ---------------------------------------------------------------------------
// split fp32 -> bf16 hi/lo (elementwise)
// ---------------------------------------------------------------------------
__global__ __launch_bounds__(256)
void split_kernel(const float* __restrict__ src, __nv_bfloat16* __restrict__ hi,
                  __nv_bfloat16* __restrict__ lo, int n)
{
    int i = blockIdx.x * 256 + threadIdx.x;
    if (i < n) {
        float v = src[i];
        __nv_bfloat16 h = __float2bfloat16(v);
        hi[i] = h;
        lo[i] = __float2bfloat16(v - __bfloat162float(h));
    }
}

// ---------------------------------------------------------------------------
// transpose + split: W [K,N] fp32 -> W^T [N,K] bf16 hi/lo
// ---------------------------------------------------------------------------
__global__ __launch_bounds__(256)
void transpose_split_kernel(const float* __restrict__ W, __nv_bfloat16* __restrict__ Thi,
                            __nv_bfloat16* __restrict__ Tlo, int K, int N)
{
    __shared__ float t[32][33];
    const int n0 = blockIdx.x * 32, k0 = blockIdx.y * 32;
    const int tx = threadIdx.x, ty = threadIdx.y;   // 32 x 8
    #pragma unroll
    for (int j = 0; j < 32; j += 8)
        t[ty + j][tx] = W[(size_t)(k0 + ty + j) * N + n0 + tx];
    __syncthreads();
    #pragma unroll
    for (int j = 0; j < 32; j += 8) {
        float v = t[tx][ty + j];
        __nv_bfloat16 h = __float2bfloat16(v);
        size_t o = (size_t)(n0 + ty + j) * K + k0 + tx;
        Thi[o] = h;
        Tlo[o] = __float2bfloat16(v - __bfloat162float(h));
    }
}

// ---------------------------------------------------------------------------
// prepass: g_qkv [B,T,3D] fp32 -> per-head split q/k/v [B,H,T,64] bf16 hi/lo
// processes float2 pairs (d stays within a head: heads are 64-wide, pairs even)
// ---------------------------------------------------------------------------
__global__ __launch_bounds__(256)
void split_qkv_kernel(const float* __restrict__ qkv,
                      __nv_bfloat16* __restrict__ qhi, __nv_bfloat16* __restrict__ qlo,
                      __nv_bfloat16* __restrict__ khi, __nv_bfloat16* __restrict__ klo,
                      __nv_bfloat16* __restrict__ vhi, __nv_bfloat16* __restrict__ vlo)
{
    const size_t i = (size_t)blockIdx.x * 256 + threadIdx.x;  // pair index
    const float2 v = reinterpret_cast<const float2*>(qkv)[i];
    const uint32_t hi = packbf(v.x, v.y);
    const uint32_t lo = packlo(v.x, v.y, hi);

    const int c2 = (int)(i % 1536);         // pair-col within 3D
    const size_t bt = i / 1536;
    const int t = (int)(bt % NT);
    const int b = (int)(bt / NT);
    const int sel = c2 / 512;               // 0=q,1=k,2=v
    const int cc = c2 % 512;                // pair within D
    const int h = cc >> 5;
    const int d2 = cc & 31;
    const size_t o = ((size_t)(b * NH + h) * NT + t) * 32 + d2;

    uint32_t* dh;
    uint32_t* dl;
    if (sel == 0)      { dh = reinterpret_cast<uint32_t*>(qhi); dl = reinterpret_cast<uint32_t*>(qlo); }
    else if (sel == 1) { dh = reinterpret_cast<uint32_t*>(khi); dl = reinterpret_cast<uint32_t*>(klo); }
    else               { dh = reinterpret_cast<uint32_t*>(vhi); dl = reinterpret_cast<uint32_t*>(vlo); }
    dh[o] = hi;
    dl[o] = lo;
}

// ---------------------------------------------------------------------------
// mma.sync bf16x3 GEMM (unchanged from R4, passing): C = A @ B^T + bias
// ---------------------------------------------------------------------------
#define STG_BYTES 40960
#define T_AHI 0
#define T_ALO 10240
#define T_BHI 20480
#define T_BLO 30720

__global__ __launch_bounds__(256)
void gemm_bf16x3(const __nv_bfloat16* __restrict__ Ahi, const __nv_bfloat16* __restrict__ Alo,
                 const __nv_bfloat16* __restrict__ Bhi, const __nv_bfloat16* __restrict__ Blo,
                 const float* __restrict__ bias, float* __restrict__ C,
                 int M, int N, int K)
{
    extern __shared__ char dynsm[];
    const uint32_t sb0 = smem_u32(dynsm);

    const int tid = threadIdx.x;
    const int wid = tid >> 5;
    const int l   = tid & 31;
    const int wm  = wid >> 1;
    const int wn  = wid & 1;
    const size_t m0 = (size_t)blockIdx.y * 128;
    const size_t n0 = (size_t)blockIdx.x * 128;

    const int r1 = tid >> 2;
    const int r2 = r1 + 64;
    const int cc = (tid & 3);
    const uint32_t sm_off1 = (uint32_t)r1 * 80 + cc * 16;
    const uint32_t sm_off2 = (uint32_t)r2 * 80 + cc * 16;

    const int nchunks = K >> 5;

    auto issue_stage = [&](int c, int buf) {
        const int kc = c << 5;
        const uint32_t sb = sb0 + buf * STG_BYTES;
        cp16(sb + T_AHI + sm_off1, Ahi + (m0 + r1) * K + kc + cc * 8);
        cp16(sb + T_AHI + sm_off2, Ahi + (m0 + r2) * K + kc + cc * 8);
        cp16(sb + T_ALO + sm_off1, Alo + (m0 + r1) * K + kc + cc * 8);
        cp16(sb + T_ALO + sm_off2, Alo + (m0 + r2) * K + kc + cc * 8);
        cp16(sb + T_BHI + sm_off1, Bhi + (n0 + r1) * K + kc + cc * 8);
        cp16(sb + T_BHI + sm_off2, Bhi + (n0 + r2) * K + kc + cc * 8);
        cp16(sb + T_BLO + sm_off1, Blo + (n0 + r1) * K + kc + cc * 8);
        cp16(sb + T_BLO + sm_off2, Blo + (n0 + r2) * K + kc + cc * 8);
        CP_COMMIT();
    };

    const int aRow = (l & 7) + ((l >> 3) & 1) * 8;
    const int aCol8 = (l >> 4) * 8;
    const int bRow = (l & 7) + ((l >> 4) & 1) * 8;
    const int bCol8 = ((l >> 3) & 1) * 8;

    float acc[2][8][4];
    #pragma unroll
    for (int mt = 0; mt < 2; mt++)
        #pragma unroll
        for (int nt = 0; nt < 8; nt++)
            #pragma unroll
            for (int k = 0; k < 4; k++) acc[mt][nt][k] = 0.f;

    issue_stage(0, 0);
    issue_stage(1, 1);

    for (int c = 0; c < nchunks; c++) {
        CP_WAIT1();
        __syncthreads();
        if (c + 2 < nchunks) issue_stage(c + 2, (c + 2) % 3);

        const uint32_t sb = sb0 + (c % 3) * STG_BYTES;
        const uint32_t aBase = sb + (uint32_t)(wm * 32 + aRow) * 80 + aCol8 * 2;
        const uint32_t bBase = sb + (uint32_t)(wn * 64 + bRow) * 80 + bCol8 * 2;

        #pragma unroll
        for (int ks = 0; ks < 2; ks++) {
            uint32_t ah[2][4], al4[2][4], bh[4][4], bl4[4][4];
            #pragma unroll
            for (int mt = 0; mt < 2; mt++) {
                ldsm4(ah[mt],  aBase + T_AHI + mt * (16 * 80) + ks * 32);
                ldsm4(al4[mt], aBase + T_ALO + mt * (16 * 80) + ks * 32);
            }
            #pragma unroll
            for (int np = 0; np < 4; np++) {
                ldsm4(bh[np],  bBase + T_BHI + np * (16 * 80) + ks * 32);
                ldsm4(bl4[np], bBase + T_BLO + np * (16 * 80) + ks * 32);
            }
            #pragma unroll
            for (int mt = 0; mt < 2; mt++)
                #pragma unroll
                for (int nt = 0; nt < 8; nt++) {
                    const int np = nt >> 1, sub = nt & 1;
                    mma_bf16(acc[mt][nt], ah[mt],  &bh[np][sub * 2]);
                    mma_bf16(acc[mt][nt], ah[mt],  &bl4[np][sub * 2]);
                    mma_bf16(acc[mt][nt], al4[mt], &bh[np][sub * 2]);
                }
        }
        __syncthreads();
    }

    #pragma unroll
    for (int mt = 0; mt < 2; mt++) {
        const size_t row0 = m0 + wm * 32 + mt * 16 + (l >> 2);
        #pragma unroll
        for (int nt = 0; nt < 8; nt++) {
            const size_t col = n0 + wn * 64 + nt * 8 + (l & 3) * 2;
            const float b0 = bias[col], b1 = bias[col + 1];
            float2 v0 = { acc[mt][nt][0] + b0, acc[mt][nt][1] + b1 };
            float2 v1 = { acc[mt][nt][2] + b0, acc[mt][nt][3] + b1 };
            *reinterpret_cast<float2*>(&C[row0 * N + col]) = v0;
            *reinterpret_cast<float2*>(&C[(row0 + 8) * N + col]) = v1;
        }
    }
}

// ---------------------------------------------------------------------------
// Tensor-core flash attention (bf16x3 for both QK^T and PV).
// Grid (16, H, B), 256 threads (8 warps x 16 q-rows). Key tile = 128.
// smem: double-buffered K/V hi/lo (2 x 72KB) + fp32 bias tile (68KB) = 217088B.
// Q tile staged in buf1 before the loop (frags extracted to registers).
// ---------------------------------------------------------------------------
#define FROWB 144                    // smem row stride bytes (64 bf16 + pad)
#define KVARR (128 * FROWB)          // 18432
#define KVBUF (4 * KVARR)            // 73728 : Khi|Klo|Vhi|Vlo
#define OFF_BIAS (2 * KVBUF)         // 147456
#define BIAS_STRB 544                // fp32 bias row stride bytes (136 words)
#define FLASH_SMEM (OFF_BIAS + 128 * BIAS_STRB)   // 217088

__global__ __launch_bounds__(256)
void flash_mma(const __nv_bfloat16* __restrict__ qhi, const __nv_bfloat16* __restrict__ qlo,
               const __nv_bfloat16* __restrict__ khi, const __nv_bfloat16* __restrict__ klo,
               const __nv_bfloat16* __restrict__ vhi, const __nv_bfloat16* __restrict__ vlo,
               const float* __restrict__ ebias,
               __nv_bfloat16* __restrict__ out_hi, __nv_bfloat16* __restrict__ out_lo)
{
    extern __shared__ char sm[];
    const uint32_t s0 = smem_u32(sm);
    const int tid = threadIdx.x, w = tid >> 5, l = tid & 31;
    const int qb = 15 - blockIdx.x;          // heavy CTAs first
    const int h = blockIdx.y, b = blockIdx.z;
    const int q0 = qb * 128;
    const size_t hoff = (size_t)(b * NH + h) * NT * NHD;

    auto issue_kv = [&](int jt2, int bsel2) {
        #pragma unroll
        for (int i = 0; i < 16; i++) {
            const int ck = tid + i * 256;            // 0..4095
            const int arr = ck >> 10;
            const int row = (ck >> 3) & 127;
            const int seg = ck & 7;
            const size_t go = hoff + (size_t)(jt2 * 128 + row) * NHD + seg * 8;
            const __nv_bfloat16* src = (arr == 0) ? khi + go : (arr == 1) ? klo + go
                                      : (arr == 2) ? vhi + go : vlo + go;
            cp16(s0 + bsel2 * KVBUF + arr * KVARR + row * FROWB + seg * 16, src);
        }
        CP_COMMIT();
    };
    auto issue_bias = [&](int jt2) {
        #pragma unroll
        for (int i = 0; i < 16; i++) {
            const int cb = tid + i * 256;            // 0..4095
            const int row = cb >> 5;
            const int seg = cb & 31;
            const float* src = ebias + ((size_t)b * NT + q0 + row) * NT + jt2 * 128 + seg * 4;
            cp16(s0 + OFF_BIAS + row * BIAS_STRB + seg * 16, src);
        }
        CP_COMMIT();
    };

    // prologue: Q -> buf1 (Khi/Klo slots), KV(0) -> buf0, bias(0)
    #pragma unroll
    for (int i = 0; i < 8; i++) {
        const int cq = tid + i * 256;                // 0..2047
        const int arr = cq >> 10;
        const int row = (cq >> 3) & 127;
        const int seg = cq & 7;
        const __nv_bfloat16* src = (arr ? qlo : qhi) + hoff + (size_t)(q0 + row) * NHD + seg * 8;
        cp16(s0 + KVBUF + arr * KVARR + row * FROWB + seg * 16, src);
    }
    CP_COMMIT();
    issue_kv(0, 0);
    issue_bias(0);

    CP_WAIT2();                 // Q arrived
    __syncthreads();

    // Q fragments (A-operand, m16k16): 4 k-steps, hi+lo
    uint32_t qh[4][4], ql4[4][4];
    {
        const uint32_t rowOff = (uint32_t)(w * 16 + (l & 7) + ((l >> 3) & 1) * 8);
        const uint32_t colB = (uint32_t)((l >> 4) * 16);
        const uint32_t qbase = s0 + KVBUF + rowOff * FROWB + colB;
        #pragma unroll
        for (int ks = 0; ks < 4; ks++) {
            ldsm4(qh[ks],  qbase + ks * 32);
            ldsm4(ql4[ks], qbase + KVARR + ks * 32);
        }
    }
    __syncthreads();            // all warps done with Q region (buf1)

    float O[8][4];
    #pragma unroll
    for (int nt = 0; nt < 8; nt++)
        #pragma unroll
        for (int k = 0; k < 4; k++) O[nt][k] = 0.f;
    float m0 = -INFINITY, m1 = -INFINITY, l0 = 0.f, l1 = 0.f;

    const int r0 = w * 16 + (l >> 2), r1 = r0 + 8;
    const int gq0 = q0 + r0, gq1 = q0 + r1;
    const uint32_t nRow = (uint32_t)((l & 7) + ((l >> 4) & 1) * 8);
    const uint32_t kColB = (uint32_t)(((l >> 3) & 1) * 16);
    const uint32_t vRowP = (uint32_t)((l & 7) + ((l >> 3) & 1) * 8);
    const uint32_t vColB = (uint32_t)(((l >> 4) & 1) * 16);

    for (int jt = 0; jt <= qb; jt++) {
        const int bsel = jt & 1;
        CP_WAIT0();
        __syncthreads();
        if (jt < qb) issue_kv(jt + 1, bsel ^ 1);

        // ---- S = Q K^T (bf16x3)
        float acc[16][4];
        #pragma unroll
        for (int nt = 0; nt < 16; nt++)
            #pragma unroll
            for (int k = 0; k < 4; k++) acc[nt][k] = 0.f;

        const uint32_t kb = s0 + bsel * KVBUF;
        #pragma unroll
        for (int ks = 0; ks < 4; ks++) {
            #pragma unroll
            for (int np = 0; np < 8; np++) {
                uint32_t khf[4], klf[4];
                const uint32_t a = kb + (np * 16 + nRow) * FROWB + kColB + ks * 32;
                ldsm4(khf, a);
                ldsm4(klf, a + KVARR);
                #pragma unroll
                for (int sub = 0; sub < 2; sub++) {
                    const int nt = np * 2 + sub;
                    mma_bf16(acc[nt], qh[ks],  &khf[sub * 2]);
                    mma_bf16(acc[nt], qh[ks],  &klf[sub * 2]);
                    mma_bf16(acc[nt], ql4[ks], &khf[sub * 2]);
                }
            }
        }

        // ---- scale + bias + causal mask + online softmax
        float mx0 = -INFINITY, mx1 = -INFINITY;
        const bool diag = (jt == qb);
        const uint32_t biasb = s0 + OFF_BIAS + (uint32_t)(2 * (l & 3)) * 4;
        #pragma unroll
        for (int nt = 0; nt < 16; nt++) {
            const uint32_t ba = biasb + (uint32_t)r0 * BIAS_STRB + nt * 32;
            float2 bv0 = *reinterpret_cast<const float2*>(sm + (ba - s0));
            float2 bv1 = *reinterpret_cast<const float2*>(sm + (ba - s0) + 8 * BIAS_STRB);
            float v0 = acc[nt][0] * 0.125f + bv0.x;
            float v1 = acc[nt][1] * 0.125f + bv0.y;
            float v2 = acc[nt][2] * 0.125f + bv1.x;
            float v3 = acc[nt][3] * 0.125f + bv1.y;
            if (diag) {
                const int kc = jt * 128 + nt * 8 + 2 * (l & 3);
                if (kc > gq0)     v0 = -1e30f;
                if (kc + 1 > gq0) v1 = -1e30f;
                if (kc > gq1)     v2 = -1e30f;
                if (kc + 1 > gq1) v3 = -1e30f;
            }
            acc[nt][0] = v0; acc[nt][1] = v1; acc[nt][2] = v2; acc[nt][3] = v3;
            mx0 = fmaxf(mx0, fmaxf(v0, v1));
            mx1 = fmaxf(mx1, fmaxf(v2, v3));
        }
        mx0 = fmaxf(mx0, __shfl_xor_sync(0xffffffff, mx0, 1));
        mx0 = fmaxf(mx0, __shfl_xor_sync(0xffffffff, mx0, 2));
        mx1 = fmaxf(mx1, __shfl_xor_sync(0xffffffff, mx1, 1));
        mx1 = fmaxf(mx1, __shfl_xor_sync(0xffffffff, mx1, 2));

        const float mn0 = fmaxf(m0, mx0), mn1 = fmaxf(m1, mx1);
        const float c0 = __expf(m0 - mn0), c1 = __expf(m1 - mn1);
        float rs0 = 0.f, rs1 = 0.f;
        #pragma unroll
        for (int nt = 0; nt < 16; nt++) {
            const float p0 = __expf(acc[nt][0] - mn0);
            const float p1 = __expf(acc[nt][1] - mn0);
            const float p2 = __expf(acc[nt][2] - mn1);
            const float p3 = __expf(acc[nt][3] - mn1);
            acc[nt][0] = p0; acc[nt][1] = p1; acc[nt][2] = p2; acc[nt][3] = p3;
            rs0 += p0 + p1;
            rs1 += p2 + p3;
        }
        rs0 += __shfl_xor_sync(0xffffffff, rs0, 1);
        rs0 += __shfl_xor_sync(0xffffffff, rs0, 2);
        rs1 += __shfl_xor_sync(0xffffffff, rs1, 1);
        rs1 += __shfl_xor_sync(0xffffffff, rs1, 2);
        l0 = l0 * c0 + rs0;
        l1 = l1 * c1 + rs1;
        m0 = mn0; m1 = mn1;
        #pragma unroll
        for (int nt = 0; nt < 8; nt++) {
            O[nt][0] *= c0; O[nt][1] *= c0; O[nt][2] *= c1; O[nt][3] *= c1;
        }

        __syncthreads();                       // bias tile consumed by all warps
        if (jt < qb) issue_bias(jt + 1);

        // ---- O += P V (bf16x3, P packed per k-step on the fly)
        const uint32_t vb = kb + 2 * KVARR;
        #pragma unroll
        for (int kk = 0; kk < 8; kk++) {
            uint32_t phi[4], plo[4];
            phi[0] = packbf(acc[2 * kk][0], acc[2 * kk][1]);
            plo[0] = packlo(acc[2 * kk][0], acc[2 * kk][1], phi[0]);
            phi[1] = packbf(acc[2 * kk][2], acc[2 * kk][3]);
            plo[1] = packlo(acc[2 * kk][2], acc[2 * kk][3], phi[1]);
            phi[2] = packbf(acc[2 * kk + 1][0], acc[2 * kk + 1][1]);
            plo[2] = packlo(acc[2 * kk + 1][0], acc[2 * kk + 1][1], phi[2]);
            phi[3] = packbf(acc[2 * kk + 1][2], acc[2 * kk + 1][3]);
            plo[3] = packlo(acc[2 * kk + 1][2], acc[2 * kk + 1][3], phi[3]);
            #pragma unroll
            for (int nn = 0; nn < 4; nn++) {
                uint32_t vhf[4], vlf[4];
                const uint32_t va = vb + (kk * 16 + vRowP) * FROWB + nn * 32 + vColB;
                ldsm4t(vhf, va);
                ldsm4t(vlf, va + KVARR);
                #pragma unroll
                for (int sub = 0; sub < 2; sub++) {
                    const int nt = nn * 2 + sub;
                    mma_bf16(O[nt], phi, &vhf[sub * 2]);
                    mma_bf16(O[nt], phi, &vlf[sub * 2]);
                    mma_bf16(O[nt], plo, &vhf[sub * 2]);
                }
            }
        }
    }

    // ---- epilogue: O/l -> bf16 hi/lo, [B,T,D] layout
    const float inv0 = 1.f / l0, inv1 = 1.f / l1;
    const size_t a0 = ((size_t)b * NT + gq0) * ND + h * NHD + 2 * (l & 3);
    const size_t a1 = ((size_t)b * NT + gq1) * ND + h * NHD + 2 * (l & 3);
    #pragma unroll
    for (int nt = 0; nt < 8; nt++) {
        const float o0 = O[nt][0] * inv0, o1 = O[nt][1] * inv0;
        const float o2 = O[nt][2] * inv1, o3 = O[nt][3] * inv1;
        const uint32_t h0 = packbf(o0, o1), lo0 = packlo(o0, o1, h0);
        const uint32_t h1 = packbf(o2, o3), lo1 = packlo(o2, o3, h1);
        *reinterpret_cast<uint32_t*>(out_hi + a0 + nt * 8) = h0;
        *reinterpret_cast<uint32_t*>(out_lo + a0 + nt * 8) = lo0;
        *reinterpret_cast<uint32_t*>(out_hi + a1 + nt * 8) = h1;
        *reinterpret_cast<uint32_t*>(out_lo + a1 + nt * 8) = lo1;
    }
}

// ---------------------------------------------------------------------------
extern "C" void kernel_launch(void* const* d_in, const int* in_sizes, int n_in,
                              void* d_out, int out_size)
{
    const float* x     = (const float*)d_in[0];
    const float* eb    = (const float*)d_in[1];
    const float* Wqkv  = (const float*)d_in[2];
    const float* bqkv  = (const float*)d_in[3];
    const float* Wout  = (const float*)d_in[4];
    const float* bout  = (const float*)d_in[5];
    float* out = (float*)d_out;

    float* qkv = nullptr;
    __nv_bfloat16 *xhi, *xlo, *wqhi, *wqlo, *wohi, *wolo, *athi, *atlo;
    __nv_bfloat16 *qhi, *qlo, *khi2, *klo2, *vhi2, *vlo2;
    cudaGetSymbolAddress((void**)&qkv,  g_qkv);
    cudaGetSymbolAddress((void**)&xhi,  g_x_hi);
    cudaGetSymbolAddress((void**)&xlo,  g_x_lo);
    cudaGetSymbolAddress((void**)&wqhi, g_wq_hi);
    cudaGetSymbolAddress((void**)&wqlo, g_wq_lo);
    cudaGetSymbolAddress((void**)&wohi, g_wo_hi);
    cudaGetSymbolAddress((void**)&wolo, g_wo_lo);
    cudaGetSymbolAddress((void**)&athi, g_att_hi);
    cudaGetSymbolAddress((void**)&atlo, g_att_lo);
    cudaGetSymbolAddress((void**)&qhi,  g_q_hi);
    cudaGetSymbolAddress((void**)&qlo,  g_q_lo);
    cudaGetSymbolAddress((void**)&khi2, g_k_hi);
    cudaGetSymbolAddress((void**)&klo2, g_k_lo);
    cudaGetSymbolAddress((void**)&vhi2, g_v_hi);
    cudaGetSymbolAddress((void**)&vlo2, g_v_lo);

    const int M = NB * NT;   // 8192

    // 0) precision splits / weight transposes
    split_kernel<<<(M * ND + 255) / 256, 256>>>(x, xhi, xlo, M * ND);
    {
        dim3 blk(32, 8);
        transpose_split_kernel<<<dim3(3 * ND / 32, ND / 32), blk>>>(Wqkv, wqhi, wqlo, ND, 3 * ND);
        transpose_split_kernel<<<dim3(ND / 32, ND / 32), blk>>>(Wout, wohi, wolo, ND, ND);
    }

    const int gemm_smem = 3 * STG_BYTES;
    cudaFuncSetAttribute(gemm_bf16x3, cudaFuncAttributeMaxDynamicSharedMemorySize, gemm_smem);

    // 1) QKV projection (tensor cores)
    gemm_bf16x3<<<dim3(3 * ND / 128, M / 128), 256, gemm_smem>>>(
        xhi, xlo, wqhi, wqlo, bqkv, qkv, M, 3 * ND, ND);

    // 1b) prepass: split + per-head reshape of q/k/v
    split_qkv_kernel<<<(int)(((size_t)M * 1536) / 256), 256>>>(
        qkv, qhi, qlo, khi2, klo2, vhi2, vlo2);

    // 2) tensor-core flash attention
    cudaFuncSetAttribute(flash_mma, cudaFuncAttributeMaxDynamicSharedMemorySize, FLASH_SMEM);
    flash_mma<<<dim3(NT / 128, NH, NB), 256, FLASH_SMEM>>>(
        qhi, qlo, khi2, klo2, vhi2, vlo2, eb, athi, atlo);

    // 3) output projection (tensor cores)
    gemm_bf16x3<<<dim3(ND / 128, M / 128), 256, gemm_smem>>>(
        athi, atlo, wohi, wolo, bout, out, M, ND, ND);
}

// round 6
// speedup vs baseline: 3.3008x; 1.7142x over previous
#include <cuda_runtime.h>
#include <cuda_bf16.h>
#include <math.h>
#include <stdint.h>

#define NB 4
#define NT 2048
#define ND 1024
#define NH 16
#define NHD 64

// ---------------------------------------------------------------------------
// scratch (allocation-free rule: __device__ globals)
// ---------------------------------------------------------------------------
__device__ __align__(256) __nv_bfloat16 g_x_hi[(size_t)NB * NT * ND];
__device__ __align__(256) __nv_bfloat16 g_x_lo[(size_t)NB * NT * ND];
__device__ __align__(256) __nv_bfloat16 g_wq_hi[(size_t)3 * ND * ND];      // Wqkv^T [3D, D]
__device__ __align__(256) __nv_bfloat16 g_wq_lo[(size_t)3 * ND * ND];
__device__ __align__(256) __nv_bfloat16 g_wo_hi[(size_t)ND * ND];          // Wout^T [D, D]
__device__ __align__(256) __nv_bfloat16 g_wo_lo[(size_t)ND * ND];
__device__ __align__(256) __nv_bfloat16 g_att_hi[(size_t)NB * NT * ND];
__device__ __align__(256) __nv_bfloat16 g_att_lo[(size_t)NB * NT * ND];
// per-head split q/k/v: [B,H,T,64] bf16 (written by QKV GEMM epilogue)
__device__ __align__(256) __nv_bfloat16 g_q_hi[(size_t)NB * NH * NT * NHD];
__device__ __align__(256) __nv_bfloat16 g_q_lo[(size_t)NB * NH * NT * NHD];
__device__ __align__(256) __nv_bfloat16 g_k_hi[(size_t)NB * NH * NT * NHD];
__device__ __align__(256) __nv_bfloat16 g_k_lo[(size_t)NB * NH * NT * NHD];
__device__ __align__(256) __nv_bfloat16 g_v_hi[(size_t)NB * NH * NT * NHD];
__device__ __align__(256) __nv_bfloat16 g_v_lo[(size_t)NB * NH * NT * NHD];
// entity bias in bf16
__device__ __align__(256) __nv_bfloat16 g_eb_bf[(size_t)NB * NT * NT];

// ---------------------------------------------------------------------------
// PTX helpers (all baseline sm_80+)
// ---------------------------------------------------------------------------
__device__ __forceinline__ uint32_t smem_u32(const void* p) {
    uint32_t a;
    asm("{ .reg .u64 t; cvta.to.shared.u64 t, %1; cvt.u32.u64 %0, t; }" : "=r"(a) : "l"(p));
    return a;
}
__device__ __forceinline__ void ldsm4(uint32_t* r, uint32_t addr) {
    asm volatile("ldmatrix.sync.aligned.m8n8.x4.shared.b16 {%0,%1,%2,%3}, [%4];"
                 : "=r"(r[0]), "=r"(r[1]), "=r"(r[2]), "=r"(r[3]) : "r"(addr));
}
__device__ __forceinline__ void ldsm4t(uint32_t* r, uint32_t addr) {
    asm volatile("ldmatrix.sync.aligned.m8n8.x4.trans.shared.b16 {%0,%1,%2,%3}, [%4];"
                 : "=r"(r[0]), "=r"(r[1]), "=r"(r[2]), "=r"(r[3]) : "r"(addr));
}
__device__ __forceinline__ void mma_bf16(float* c, const uint32_t* a, const uint32_t* b) {
    asm volatile(
        "mma.sync.aligned.m16n8k16.row.col.f32.bf16.bf16.f32 "
        "{%0,%1,%2,%3}, {%4,%5,%6,%7}, {%8,%9}, {%0,%1,%2,%3};"
        : "+f"(c[0]), "+f"(c[1]), "+f"(c[2]), "+f"(c[3])
        : "r"(a[0]), "r"(a[1]), "r"(a[2]), "r"(a[3]), "r"(b[0]), "r"(b[1]));
}
__device__ __forceinline__ void cp16(uint32_t smem, const void* g) {
    asm volatile("cp.async.cg.shared.global [%0], [%1], 16;" :: "r"(smem), "l"(g));
}
#define CP_COMMIT() asm volatile("cp.async.commit_group;" ::: "memory")
#define CP_WAIT1()  asm volatile("cp.async.wait_group 1;" ::: "memory")
#define CP_WAIT0()  asm volatile("cp.async.wait_group 0;" ::: "memory")
#define CP_WAIT2()  asm volatile("cp.async.wait_group 2;" ::: "memory")

__device__ __forceinline__ uint32_t packbf(float a, float b) {
    __nv_bfloat162 t = __float22bfloat162_rn(make_float2(a, b));
    return *reinterpret_cast<uint32_t*>(&t);
}
__device__ __forceinline__ uint32_t packlo(float a, float b, uint32_t hi) {
    __nv_bfloat162 h = *reinterpret_cast<__nv_bfloat162*>(&hi);
    float2 hf = __bfloat1622float2(h);
    return packbf(a - hf.x, b - hf.y);
}

// ---------------------------------------------------------------------------
// split fp32 -> bf16 hi/lo (elementwise)
// ---------------------------------------------------------------------------
__global__ __launch_bounds__(256)
void split_kernel(const float* __restrict__ src, __nv_bfloat16* __restrict__ hi,
                  __nv_bfloat16* __restrict__ lo, int n)
{
    int i = blockIdx.x * 256 + threadIdx.x;
    if (i < n) {
        float v = src[i];
        __nv_bfloat16 h = __float2bfloat16(v);
        hi[i] = h;
        lo[i] = __float2bfloat16(v - __bfloat162float(h));
    }
}

// ---------------------------------------------------------------------------
// entity bias fp32 -> bf16 (4 elems/thread)
// ---------------------------------------------------------------------------
__global__ __launch_bounds__(256)
void bias_to_bf16_kernel(const float* __restrict__ src, __nv_bfloat16* __restrict__ dst)
{
    const size_t i = ((size_t)blockIdx.x * 256 + threadIdx.x) * 4;
    const float4 v = *reinterpret_cast<const float4*>(src + i);
    uint32_t p0 = packbf(v.x, v.y);
    uint32_t p1 = packbf(v.z, v.w);
    *reinterpret_cast<uint32_t*>(dst + i)     = p0;
    *reinterpret_cast<uint32_t*>(dst + i + 2) = p1;
}

// ---------------------------------------------------------------------------
// transpose + split: W [K,N] fp32 -> W^T [N,K] bf16 hi/lo
// ---------------------------------------------------------------------------
__global__ __launch_bounds__(256)
void transpose_split_kernel(const float* __restrict__ W, __nv_bfloat16* __restrict__ Thi,
                            __nv_bfloat16* __restrict__ Tlo, int K, int N)
{
    __shared__ float t[32][33];
    const int n0 = blockIdx.x * 32, k0 = blockIdx.y * 32;
    const int tx = threadIdx.x, ty = threadIdx.y;   // 32 x 8
    #pragma unroll
    for (int j = 0; j < 32; j += 8)
        t[ty + j][tx] = W[(size_t)(k0 + ty + j) * N + n0 + tx];
    __syncthreads();
    #pragma unroll
    for (int j = 0; j < 32; j += 8) {
        float v = t[tx][ty + j];
        __nv_bfloat16 h = __float2bfloat16(v);
        size_t o = (size_t)(n0 + ty + j) * K + k0 + tx;
        Thi[o] = h;
        Tlo[o] = __float2bfloat16(v - __bfloat162float(h));
    }
}

// ---------------------------------------------------------------------------
// mma.sync bf16x3 GEMM: 256 thr (8 warps 4x2), tile 128x128, BK=32,
// 2-stage cp.async pipeline (80KB smem) -> 2 CTAs/SM.
// MODE 0: C = A@B^T + bias (fp32)
// MODE 1: QKV epilogue -> per-head split q/k/v bf16 hi/lo (+bias), C unused
// ---------------------------------------------------------------------------
#define STG_BYTES 40960
#define T_AHI 0
#define T_ALO 10240
#define T_BHI 20480
#define T_BLO 30720

template <int MODE>
__global__ __launch_bounds__(256, 2)
void gemm_bf16x3(const __nv_bfloat16* __restrict__ Ahi, const __nv_bfloat16* __restrict__ Alo,
                 const __nv_bfloat16* __restrict__ Bhi, const __nv_bfloat16* __restrict__ Blo,
                 const float* __restrict__ bias, float* __restrict__ C,
                 __nv_bfloat16* __restrict__ qhi, __nv_bfloat16* __restrict__ qlo,
                 __nv_bfloat16* __restrict__ khi, __nv_bfloat16* __restrict__ klo,
                 __nv_bfloat16* __restrict__ vhi, __nv_bfloat16* __restrict__ vlo,
                 int M, int N, int K)
{
    extern __shared__ char dynsm[];
    const uint32_t sb0 = smem_u32(dynsm);

    const int tid = threadIdx.x;
    const int wid = tid >> 5;
    const int l   = tid & 31;
    const int wm  = wid >> 1;
    const int wn  = wid & 1;
    const size_t m0 = (size_t)blockIdx.y * 128;
    const size_t n0 = (size_t)blockIdx.x * 128;

    const int r1 = tid >> 2;
    const int r2 = r1 + 64;
    const int cc = (tid & 3);
    const uint32_t sm_off1 = (uint32_t)r1 * 80 + cc * 16;
    const uint32_t sm_off2 = (uint32_t)r2 * 80 + cc * 16;

    const int nchunks = K >> 5;

    auto issue_stage = [&](int c, int buf) {
        const int kc = c << 5;
        const uint32_t sb = sb0 + buf * STG_BYTES;
        cp16(sb + T_AHI + sm_off1, Ahi + (m0 + r1) * K + kc + cc * 8);
        cp16(sb + T_AHI + sm_off2, Ahi + (m0 + r2) * K + kc + cc * 8);
        cp16(sb + T_ALO + sm_off1, Alo + (m0 + r1) * K + kc + cc * 8);
        cp16(sb + T_ALO + sm_off2, Alo + (m0 + r2) * K + kc + cc * 8);
        cp16(sb + T_BHI + sm_off1, Bhi + (n0 + r1) * K + kc + cc * 8);
        cp16(sb + T_BHI + sm_off2, Bhi + (n0 + r2) * K + kc + cc * 8);
        cp16(sb + T_BLO + sm_off1, Blo + (n0 + r1) * K + kc + cc * 8);
        cp16(sb + T_BLO + sm_off2, Blo + (n0 + r2) * K + kc + cc * 8);
        CP_COMMIT();
    };

    const int aRow = (l & 7) + ((l >> 3) & 1) * 8;
    const int aCol8 = (l >> 4) * 8;
    const int bRow = (l & 7) + ((l >> 4) & 1) * 8;
    const int bCol8 = ((l >> 3) & 1) * 8;

    float acc[2][8][4];
    #pragma unroll
    for (int mt = 0; mt < 2; mt++)
        #pragma unroll
        for (int nt = 0; nt < 8; nt++)
            #pragma unroll
            for (int k = 0; k < 4; k++) acc[mt][nt][k] = 0.f;

    issue_stage(0, 0);

    for (int c = 0; c < nchunks; c++) {
        if (c + 1 < nchunks) {
            issue_stage(c + 1, (c + 1) & 1);   // prev compute on this buf done (trailing sync)
            CP_WAIT1();                        // stage c arrived (c+1 may be in flight)
        } else {
            CP_WAIT0();                        // tail: must wait the final stage fully
        }
        __syncthreads();

        const uint32_t sb = sb0 + (c & 1) * STG_BYTES;
        const uint32_t aBase = sb + (uint32_t)(wm * 32 + aRow) * 80 + aCol8 * 2;
        const uint32_t bBase = sb + (uint32_t)(wn * 64 + bRow) * 80 + bCol8 * 2;

        #pragma unroll
        for (int ks = 0; ks < 2; ks++) {
            uint32_t ah[2][4], al4[2][4];
            #pragma unroll
            for (int mt = 0; mt < 2; mt++) {
                ldsm4(ah[mt],  aBase + T_AHI + mt * (16 * 80) + ks * 32);
                ldsm4(al4[mt], aBase + T_ALO + mt * (16 * 80) + ks * 32);
            }
            #pragma unroll
            for (int np = 0; np < 4; np++) {
                uint32_t bh[4], bl4[4];
                ldsm4(bh,  bBase + T_BHI + np * (16 * 80) + ks * 32);
                ldsm4(bl4, bBase + T_BLO + np * (16 * 80) + ks * 32);
                #pragma unroll
                for (int mt = 0; mt < 2; mt++)
                    #pragma unroll
                    for (int sub = 0; sub < 2; sub++) {
                        const int nt = np * 2 + sub;
                        mma_bf16(acc[mt][nt], ah[mt],  &bh[sub * 2]);
                        mma_bf16(acc[mt][nt], ah[mt],  &bl4[sub * 2]);
                        mma_bf16(acc[mt][nt], al4[mt], &bh[sub * 2]);
                    }
            }
        }
        __syncthreads();
    }

    if (MODE == 0) {
        #pragma unroll
        for (int mt = 0; mt < 2; mt++) {
            const size_t row0 = m0 + wm * 32 + mt * 16 + (l >> 2);
            #pragma unroll
            for (int nt = 0; nt < 8; nt++) {
                const size_t col = n0 + wn * 64 + nt * 8 + (l & 3) * 2;
                const float b0 = bias[col], b1 = bias[col + 1];
                float2 v0 = { acc[mt][nt][0] + b0, acc[mt][nt][1] + b1 };
                float2 v1 = { acc[mt][nt][2] + b0, acc[mt][nt][3] + b1 };
                *reinterpret_cast<float2*>(&C[row0 * N + col]) = v0;
                *reinterpret_cast<float2*>(&C[(row0 + 8) * N + col]) = v1;
            }
        }
    } else {
        // per-head split epilogue: col band (64 wide) lies in one head of one of q/k/v
        const int colbase = (int)n0 + wn * 64;
        const int sel = colbase >> 10;             // 0=q,1=k,2=v
        const int head = (colbase >> 6) & 15;
        __nv_bfloat16* dh = (sel == 0) ? qhi : (sel == 1) ? khi : vhi;
        __nv_bfloat16* dl = (sel == 0) ? qlo : (sel == 1) ? klo : vlo;
        #pragma unroll
        for (int mt = 0; mt < 2; mt++) {
            const int row0 = (int)m0 + wm * 32 + mt * 16 + (l >> 2);
            const int bb = row0 >> 11;             // batch (rows of 2048)
            const int t0 = row0 & 2047;
            const size_t base = ((size_t)(bb * NH + head) * NT + t0) * NHD;
            #pragma unroll
            for (int nt = 0; nt < 8; nt++) {
                const int col = colbase + nt * 8 + (l & 3) * 2;
                const int d = col & 63;
                const float b0 = bias[col], b1 = bias[col + 1];
                const float v0 = acc[mt][nt][0] + b0, v1 = acc[mt][nt][1] + b1;
                const float v2 = acc[mt][nt][2] + b0, v3 = acc[mt][nt][3] + b1;
                const uint32_t h0 = packbf(v0, v1), lo0 = packlo(v0, v1, h0);
                const uint32_t h1 = packbf(v2, v3), lo1 = packlo(v2, v3, h1);
                *reinterpret_cast<uint32_t*>(dh + base + d)            = h0;
                *reinterpret_cast<uint32_t*>(dl + base + d)            = lo0;
                *reinterpret_cast<uint32_t*>(dh + base + 8 * NHD + d)  = h1;
                *reinterpret_cast<uint32_t*>(dl + base + 8 * NHD + d)  = lo1;
            }
        }
    }
}

// ---------------------------------------------------------------------------
// Tensor-core flash attention (bf16x3 QK^T and PV). Bias tile now bf16.
// Grid (16, H, B), 256 threads. Key tile = 128.
// smem: 2 x 72KB KV (hi/lo) + 34KB bf16 bias = 182272 B.
// ---------------------------------------------------------------------------
#define FROWB 144
#define KVARR (128 * FROWB)          // 18432
#define KVBUF (4 * KVARR)            // 73728 : Khi|Klo|Vhi|Vlo
#define OFF_BIAS (2 * KVBUF)         // 147456
#define BIAS_STRB 272                // bf16 bias row stride bytes (128*2 + 16)
#define FLASH_SMEM (OFF_BIAS + 128 * BIAS_STRB)   // 182272

__global__ __launch_bounds__(256)
void flash_mma(const __nv_bfloat16* __restrict__ qhi, const __nv_bfloat16* __restrict__ qlo,
               const __nv_bfloat16* __restrict__ khi, const __nv_bfloat16* __restrict__ klo,
               const __nv_bfloat16* __restrict__ vhi, const __nv_bfloat16* __restrict__ vlo,
               const __nv_bfloat16* __restrict__ ebias,
               __nv_bfloat16* __restrict__ out_hi, __nv_bfloat16* __restrict__ out_lo)
{
    extern __shared__ char sm[];
    const uint32_t s0 = smem_u32(sm);
    const int tid = threadIdx.x, w = tid >> 5, l = tid & 31;
    const int qb = 15 - blockIdx.x;          // heavy CTAs first
    const int h = blockIdx.y, b = blockIdx.z;
    const int q0 = qb * 128;
    const size_t hoff = (size_t)(b * NH + h) * NT * NHD;

    auto issue_kv = [&](int jt2, int bsel2) {
        #pragma unroll
        for (int i = 0; i < 16; i++) {
            const int ck = tid + i * 256;            // 0..4095
            const int arr = ck >> 10;
            const int row = (ck >> 3) & 127;
            const int seg = ck & 7;
            const size_t go = hoff + (size_t)(jt2 * 128 + row) * NHD + seg * 8;
            const __nv_bfloat16* src = (arr == 0) ? khi + go : (arr == 1) ? klo + go
                                      : (arr == 2) ? vhi + go : vlo + go;
            cp16(s0 + bsel2 * KVBUF + arr * KVARR + row * FROWB + seg * 16, src);
        }
        CP_COMMIT();
    };
    auto issue_bias = [&](int jt2) {
        #pragma unroll
        for (int i = 0; i < 8; i++) {
            const int cb = tid + i * 256;            // 0..2047
            const int row = cb >> 4;
            const int seg = cb & 15;
            const __nv_bfloat16* src =
                ebias + ((size_t)b * NT + q0 + row) * NT + jt2 * 128 + seg * 8;
            cp16(s0 + OFF_BIAS + row * BIAS_STRB + seg * 16, src);
        }
        CP_COMMIT();
    };

    // prologue: Q -> buf1 (Khi/Klo slots), KV(0) -> buf0, bias(0)
    #pragma unroll
    for (int i = 0; i < 8; i++) {
        const int cq = tid + i * 256;                // 0..2047
        const int arr = cq >> 10;
        const int row = (cq >> 3) & 127;
        const int seg = cq & 7;
        const __nv_bfloat16* src = (arr ? qlo : qhi) + hoff + (size_t)(q0 + row) * NHD + seg * 8;
        cp16(s0 + KVBUF + arr * KVARR + row * FROWB + seg * 16, src);
    }
    CP_COMMIT();
    issue_kv(0, 0);
    issue_bias(0);

    CP_WAIT2();                 // Q arrived
    __syncthreads();

    // Q fragments (A-operand, m16k16): 4 k-steps, hi+lo
    uint32_t qh[4][4], ql4[4][4];
    {
        const uint32_t rowOff = (uint32_t)(w * 16 + (l & 7) + ((l >> 3) & 1) * 8);
        const uint32_t colB = (uint32_t)((l >> 4) * 16);
        const uint32_t qbase = s0 + KVBUF + rowOff * FROWB + colB;
        #pragma unroll
        for (int ks = 0; ks < 4; ks++) {
            ldsm4(qh[ks],  qbase + ks * 32);
            ldsm4(ql4[ks], qbase + KVARR + ks * 32);
        }
    }
    __syncthreads();            // all warps done with Q region (buf1)

    float O[8][4];
    #pragma unroll
    for (int nt = 0; nt < 8; nt++)
        #pragma unroll
        for (int k = 0; k < 4; k++) O[nt][k] = 0.f;
    float m0 = -INFINITY, m1 = -INFINITY, l0 = 0.f, l1 = 0.f;

    const int r0 = w * 16 + (l >> 2), r1 = r0 + 8;
    const int gq0 = q0 + r0, gq1 = q0 + r1;
    const uint32_t nRow = (uint32_t)((l & 7) + ((l >> 4) & 1) * 8);
    const uint32_t kColB = (uint32_t)(((l >> 3) & 1) * 16);
    const uint32_t vRowP = (uint32_t)((l & 7) + ((l >> 3) & 1) * 8);
    const uint32_t vColB = (uint32_t)(((l >> 4) & 1) * 16);

    for (int jt = 0; jt <= qb; jt++) {
        const int bsel = jt & 1;
        CP_WAIT0();
        __syncthreads();
        if (jt < qb) issue_kv(jt + 1, bsel ^ 1);

        // ---- S = Q K^T (bf16x3)
        float acc[16][4];
        #pragma unroll
        for (int nt = 0; nt < 16; nt++)
            #pragma unroll
            for (int k = 0; k < 4; k++) acc[nt][k] = 0.f;

        const uint32_t kb = s0 + bsel * KVBUF;
        #pragma unroll
        for (int ks = 0; ks < 4; ks++) {
            #pragma unroll
            for (int np = 0; np < 8; np++) {
                uint32_t khf[4], klf[4];
                const uint32_t a = kb + (np * 16 + nRow) * FROWB + kColB + ks * 32;
                ldsm4(khf, a);
                ldsm4(klf, a + KVARR);
                #pragma unroll
                for (int sub = 0; sub < 2; sub++) {
                    const int nt = np * 2 + sub;
                    mma_bf16(acc[nt], qh[ks],  &khf[sub * 2]);
                    mma_bf16(acc[nt], qh[ks],  &klf[sub * 2]);
                    mma_bf16(acc[nt], ql4[ks], &khf[sub * 2]);
                }
            }
        }

        // ---- scale + bias (bf16) + causal mask + online softmax
        float mx0 = -INFINITY, mx1 = -INFINITY;
        const bool diag = (jt == qb);
        const uint32_t biasOff = (uint32_t)(OFF_BIAS + (l & 3) * 4);
        #pragma unroll
        for (int nt = 0; nt < 16; nt++) {
            const char* bp = sm + biasOff + (uint32_t)r0 * BIAS_STRB + nt * 16;
            float2 bv0 = __bfloat1622float2(*reinterpret_cast<const __nv_bfloat162*>(bp));
            float2 bv1 = __bfloat1622float2(
                *reinterpret_cast<const __nv_bfloat162*>(bp + 8 * BIAS_STRB));
            float v0 = acc[nt][0] * 0.125f + bv0.x;
            float v1 = acc[nt][1] * 0.125f + bv0.y;
            float v2 = acc[nt][2] * 0.125f + bv1.x;
            float v3 = acc[nt][3] * 0.125f + bv1.y;
            if (diag) {
                const int kc = jt * 128 + nt * 8 + 2 * (l & 3);
                if (kc > gq0)     v0 = -1e30f;
                if (kc + 1 > gq0) v1 = -1e30f;
                if (kc > gq1)     v2 = -1e30f;
                if (kc + 1 > gq1) v3 = -1e30f;
            }
            acc[nt][0] = v0; acc[nt][1] = v1; acc[nt][2] = v2; acc[nt][3] = v3;
            mx0 = fmaxf(mx0, fmaxf(v0, v1));
            mx1 = fmaxf(mx1, fmaxf(v2, v3));
        }
        mx0 = fmaxf(mx0, __shfl_xor_sync(0xffffffff, mx0, 1));
        mx0 = fmaxf(mx0, __shfl_xor_sync(0xffffffff, mx0, 2));
        mx1 = fmaxf(mx1, __shfl_xor_sync(0xffffffff, mx1, 1));
        mx1 = fmaxf(mx1, __shfl_xor_sync(0xffffffff, mx1, 2));

        const float mn0 = fmaxf(m0, mx0), mn1 = fmaxf(m1, mx1);
        const float c0 = __expf(m0 - mn0), c1 = __expf(m1 - mn1);
        float rs0 = 0.f, rs1 = 0.f;
        #pragma unroll
        for (int nt = 0; nt < 16; nt++) {
            const float p0 = __expf(acc[nt][0] - mn0);
            const float p1 = __expf(acc[nt][1] - mn0);
            const float p2 = __expf(acc[nt][2] - mn1);
            const float p3 = __expf(acc[nt][3] - mn1);
            acc[nt][0] = p0; acc[nt][1] = p1; acc[nt][2] = p2; acc[nt][3] = p3;
            rs0 += p0 + p1;
            rs1 += p2 + p3;
        }
        rs0 += __shfl_xor_sync(0xffffffff, rs0, 1);
        rs0 += __shfl_xor_sync(0xffffffff, rs0, 2);
        rs1 += __shfl_xor_sync(0xffffffff, rs1, 1);
        rs1 += __shfl_xor_sync(0xffffffff, rs1, 2);
        l0 = l0 * c0 + rs0;
        l1 = l1 * c1 + rs1;
        m0 = mn0; m1 = mn1;
        #pragma unroll
        for (int nt = 0; nt < 8; nt++) {
            O[nt][0] *= c0; O[nt][1] *= c0; O[nt][2] *= c1; O[nt][3] *= c1;
        }

        __syncthreads();                       // bias tile consumed by all warps
        if (jt < qb) issue_bias(jt + 1);

        // ---- O += P V (bf16x3, P packed per k-step on the fly)
        const uint32_t vb = kb + 2 * KVARR;
        #pragma unroll
        for (int kk = 0; kk < 8; kk++) {
            uint32_t phi[4], plo[4];
            phi[0] = packbf(acc[2 * kk][0], acc[2 * kk][1]);
            plo[0] = packlo(acc[2 * kk][0], acc[2 * kk][1], phi[0]);
            phi[1] = packbf(acc[2 * kk][2], acc[2 * kk][3]);
            plo[1] = packlo(acc[2 * kk][2], acc[2 * kk][3], phi[1]);
            phi[2] = packbf(acc[2 * kk + 1][0], acc[2 * kk + 1][1]);
            plo[2] = packlo(acc[2 * kk + 1][0], acc[2 * kk + 1][1], phi[2]);
            phi[3] = packbf(acc[2 * kk + 1][2], acc[2 * kk + 1][3]);
            plo[3] = packlo(acc[2 * kk + 1][2], acc[2 * kk + 1][3], phi[3]);
            #pragma unroll
            for (int nn = 0; nn < 4; nn++) {
                uint32_t vhf[4], vlf[4];
                const uint32_t va = vb + (kk * 16 + vRowP) * FROWB + nn * 32 + vColB;
                ldsm4t(vhf, va);
                ldsm4t(vlf, va + KVARR);
                #pragma unroll
                for (int sub = 0; sub < 2; sub++) {
                    const int nt = nn * 2 + sub;
                    mma_bf16(O[nt], phi, &vhf[sub * 2]);
                    mma_bf16(O[nt], phi, &vlf[sub * 2]);
                    mma_bf16(O[nt], plo, &vhf[sub * 2]);
                }
            }
        }
    }

    // ---- epilogue: O/l -> bf16 hi/lo, [B,T,D] layout
    const float inv0 = 1.f / l0, inv1 = 1.f / l1;
    const size_t a0 = ((size_t)b * NT + gq0) * ND + h * NHD + 2 * (l & 3);
    const size_t a1 = ((size_t)b * NT + gq1) * ND + h * NHD + 2 * (l & 3);
    #pragma unroll
    for (int nt = 0; nt < 8; nt++) {
        const float o0 = O[nt][0] * inv0, o1 = O[nt][1] * inv0;
        const float o2 = O[nt][2] * inv1, o3 = O[nt][3] * inv1;
        const uint32_t h0 = packbf(o0, o1), lo0 = packlo(o0, o1, h0);
        const uint32_t h1 = packbf(o2, o3), lo1 = packlo(o2, o3, h1);
        *reinterpret_cast<uint32_t*>(out_hi + a0 + nt * 8) = h0;
        *reinterpret_cast<uint32_t*>(out_lo + a0 + nt * 8) = lo0;
        *reinterpret_cast<uint32_t*>(out_hi + a1 + nt * 8) = h1;
        *reinterpret_cast<uint32_t*>(out_lo + a1 + nt * 8) = lo1;
    }
}

// ---------------------------------------------------------------------------
extern "C" void kernel_launch(void* const* d_in, const int* in_sizes, int n_in,
                              void* d_out, int out_size)
{
    const float* x     = (const float*)d_in[0];
    const float* eb    = (const float*)d_in[1];
    const float* Wqkv  = (const float*)d_in[2];
    const float* bqkv  = (const float*)d_in[3];
    const float* Wout  = (const float*)d_in[4];
    const float* bout  = (const float*)d_in[5];
    float* out = (float*)d_out;

    __nv_bfloat16 *xhi, *xlo, *wqhi, *wqlo, *wohi, *wolo, *athi, *atlo;
    __nv_bfloat16 *qhi, *qlo, *khi2, *klo2, *vhi2, *vlo2, *ebbf;
    cudaGetSymbolAddress((void**)&xhi,  g_x_hi);
    cudaGetSymbolAddress((void**)&xlo,  g_x_lo);
    cudaGetSymbolAddress((void**)&wqhi, g_wq_hi);
    cudaGetSymbolAddress((void**)&wqlo, g_wq_lo);
    cudaGetSymbolAddress((void**)&wohi, g_wo_hi);
    cudaGetSymbolAddress((void**)&wolo, g_wo_lo);
    cudaGetSymbolAddress((void**)&athi, g_att_hi);
    cudaGetSymbolAddress((void**)&atlo, g_att_lo);
    cudaGetSymbolAddress((void**)&qhi,  g_q_hi);
    cudaGetSymbolAddress((void**)&qlo,  g_q_lo);
    cudaGetSymbolAddress((void**)&khi2, g_k_hi);
    cudaGetSymbolAddress((void**)&klo2, g_k_lo);
    cudaGetSymbolAddress((void**)&vhi2, g_v_hi);
    cudaGetSymbolAddress((void**)&vlo2, g_v_lo);
    cudaGetSymbolAddress((void**)&ebbf, g_eb_bf);

    const int M = NB * NT;   // 8192

    // 0) prepasses: x split, W transposes+split, bias -> bf16
    split_kernel<<<(M * ND + 255) / 256, 256>>>(x, xhi, xlo, M * ND);
    {
        dim3 blk(32, 8);
        transpose_split_kernel<<<dim3(3 * ND / 32, ND / 32), blk>>>(Wqkv, wqhi, wqlo, ND, 3 * ND);
        transpose_split_kernel<<<dim3(ND / 32, ND / 32), blk>>>(Wout, wohi, wolo, ND, ND);
    }
    bias_to_bf16_kernel<<<(int)(((size_t)NB * NT * NT) / 4 / 256), 256>>>(eb, ebbf);

    const int gemm_smem = 2 * STG_BYTES;   // 81920 -> 2 CTAs/SM
    cudaFuncSetAttribute(gemm_bf16x3<0>, cudaFuncAttributeMaxDynamicSharedMemorySize, gemm_smem);
    cudaFuncSetAttribute(gemm_bf16x3<1>, cudaFuncAttributeMaxDynamicSharedMemorySize, gemm_smem);

    // 1) QKV projection, fused per-head split epilogue
    gemm_bf16x3<1><<<dim3(3 * ND / 128, M / 128), 256, gemm_smem>>>(
        xhi, xlo, wqhi, wqlo, bqkv, nullptr,
        qhi, qlo, khi2, klo2, vhi2, vlo2, M, 3 * ND, ND);

    // 2) tensor-core flash attention
    cudaFuncSetAttribute(flash_mma, cudaFuncAttributeMaxDynamicSharedMemorySize, FLASH_SMEM);
    flash_mma<<<dim3(NT / 128, NH, NB), 256, FLASH_SMEM>>>(
        qhi, qlo, khi2, klo2, vhi2, vlo2, ebbf, athi, atlo);

    // 3) output projection (fp32 out + bias)
    gemm_bf16x3<0><<<dim3(ND / 128, M / 128), 256, gemm_smem>>>(
        athi, atlo, wohi, wolo, bout, out,
        nullptr, nullptr, nullptr, nullptr, nullptr, nullptr, M, ND, ND);
}

// round 7
// speedup vs baseline: 3.3493x; 1.0147x over previous
#include <cuda_runtime.h>
#include <cuda_bf16.h>
#include <math.h>
#include <stdint.h>

#define NB 4
#define NT 2048
#define ND 1024
#define NH 16
#define NHD 64

// ---------------------------------------------------------------------------
// scratch (allocation-free rule: __device__ globals)
// ---------------------------------------------------------------------------
__device__ __align__(256) __nv_bfloat16 g_x_hi[(size_t)NB * NT * ND];
__device__ __align__(256) __nv_bfloat16 g_x_lo[(size_t)NB * NT * ND];
__device__ __align__(256) __nv_bfloat16 g_wq_hi[(size_t)3 * ND * ND];      // Wqkv^T [3D, D]
__device__ __align__(256) __nv_bfloat16 g_wq_lo[(size_t)3 * ND * ND];
__device__ __align__(256) __nv_bfloat16 g_wo_hi[(size_t)ND * ND];          // Wout^T [D, D]
__device__ __align__(256) __nv_bfloat16 g_wo_lo[(size_t)ND * ND];
__device__ __align__(256) __nv_bfloat16 g_att_hi[(size_t)NB * NT * ND];
__device__ __align__(256) __nv_bfloat16 g_att_lo[(size_t)NB * NT * ND];
// per-head split q/k/v: [B,H,T,64] bf16 (written by QKV GEMM epilogue)
__device__ __align__(256) __nv_bfloat16 g_q_hi[(size_t)NB * NH * NT * NHD];
__device__ __align__(256) __nv_bfloat16 g_q_lo[(size_t)NB * NH * NT * NHD];
__device__ __align__(256) __nv_bfloat16 g_k_hi[(size_t)NB * NH * NT * NHD];
__device__ __align__(256) __nv_bfloat16 g_k_lo[(size_t)NB * NH * NT * NHD];
__device__ __align__(256) __nv_bfloat16 g_v_hi[(size_t)NB * NH * NT * NHD];
__device__ __align__(256) __nv_bfloat16 g_v_lo[(size_t)NB * NH * NT * NHD];
// entity bias in bf16
__device__ __align__(256) __nv_bfloat16 g_eb_bf[(size_t)NB * NT * NT];

// ---------------------------------------------------------------------------
// PTX helpers (all baseline sm_80+)
// ---------------------------------------------------------------------------
__device__ __forceinline__ uint32_t smem_u32(const void* p) {
    uint32_t a;
    asm("{ .reg .u64 t; cvta.to.shared.u64 t, %1; cvt.u32.u64 %0, t; }" : "=r"(a) : "l"(p));
    return a;
}
__device__ __forceinline__ void ldsm4(uint32_t* r, uint32_t addr) {
    asm volatile("ldmatrix.sync.aligned.m8n8.x4.shared.b16 {%0,%1,%2,%3}, [%4];"
                 : "=r"(r[0]), "=r"(r[1]), "=r"(r[2]), "=r"(r[3]) : "r"(addr));
}
__device__ __forceinline__ void ldsm4t(uint32_t* r, uint32_t addr) {
    asm volatile("ldmatrix.sync.aligned.m8n8.x4.trans.shared.b16 {%0,%1,%2,%3}, [%4];"
                 : "=r"(r[0]), "=r"(r[1]), "=r"(r[2]), "=r"(r[3]) : "r"(addr));
}
__device__ __forceinline__ void mma_bf16(float* c, const uint32_t* a, const uint32_t* b) {
    asm volatile(
        "mma.sync.aligned.m16n8k16.row.col.f32.bf16.bf16.f32 "
        "{%0,%1,%2,%3}, {%4,%5,%6,%7}, {%8,%9}, {%0,%1,%2,%3};"
        : "+f"(c[0]), "+f"(c[1]), "+f"(c[2]), "+f"(c[3])
        : "r"(a[0]), "r"(a[1]), "r"(a[2]), "r"(a[3]), "r"(b[0]), "r"(b[1]));
}
__device__ __forceinline__ void cp16(uint32_t smem, const void* g) {
    asm volatile("cp.async.cg.shared.global [%0], [%1], 16;" :: "r"(smem), "l"(g));
}
#define CP_COMMIT() asm volatile("cp.async.commit_group;" ::: "memory")
#define CP_WAIT1()  asm volatile("cp.async.wait_group 1;" ::: "memory")
#define CP_WAIT0()  asm volatile("cp.async.wait_group 0;" ::: "memory")
#define CP_WAIT2()  asm volatile("cp.async.wait_group 2;" ::: "memory")

__device__ __forceinline__ uint32_t packbf(float a, float b) {
    __nv_bfloat162 t = __float22bfloat162_rn(make_float2(a, b));
    return *reinterpret_cast<uint32_t*>(&t);
}
__device__ __forceinline__ uint32_t packlo(float a, float b, uint32_t hi) {
    __nv_bfloat162 h = *reinterpret_cast<__nv_bfloat162*>(&hi);
    float2 hf = __bfloat1622float2(h);
    return packbf(a - hf.x, b - hf.y);
}

// ---------------------------------------------------------------------------
// prepasses
// ---------------------------------------------------------------------------
__global__ __launch_bounds__(256)
void split_kernel(const float* __restrict__ src, __nv_bfloat16* __restrict__ hi,
                  __nv_bfloat16* __restrict__ lo, int n)
{
    int i = blockIdx.x * 256 + threadIdx.x;
    if (i < n) {
        float v = src[i];
        __nv_bfloat16 h = __float2bfloat16(v);
        hi[i] = h;
        lo[i] = __float2bfloat16(v - __bfloat162float(h));
    }
}

__global__ __launch_bounds__(256)
void bias_to_bf16_kernel(const float* __restrict__ src, __nv_bfloat16* __restrict__ dst)
{
    const size_t i = ((size_t)blockIdx.x * 256 + threadIdx.x) * 4;
    const float4 v = *reinterpret_cast<const float4*>(src + i);
    uint32_t p0 = packbf(v.x, v.y);
    uint32_t p1 = packbf(v.z, v.w);
    *reinterpret_cast<uint32_t*>(dst + i)     = p0;
    *reinterpret_cast<uint32_t*>(dst + i + 2) = p1;
}

__global__ __launch_bounds__(256)
void transpose_split_kernel(const float* __restrict__ W, __nv_bfloat16* __restrict__ Thi,
                            __nv_bfloat16* __restrict__ Tlo, int K, int N)
{
    __shared__ float t[32][33];
    const int n0 = blockIdx.x * 32, k0 = blockIdx.y * 32;
    const int tx = threadIdx.x, ty = threadIdx.y;   // 32 x 8
    #pragma unroll
    for (int j = 0; j < 32; j += 8)
        t[ty + j][tx] = W[(size_t)(k0 + ty + j) * N + n0 + tx];
    __syncthreads();
    #pragma unroll
    for (int j = 0; j < 32; j += 8) {
        float v = t[tx][ty + j];
        __nv_bfloat16 h = __float2bfloat16(v);
        size_t o = (size_t)(n0 + ty + j) * K + k0 + tx;
        Thi[o] = h;
        Tlo[o] = __float2bfloat16(v - __bfloat162float(h));
    }
}

// ---------------------------------------------------------------------------
// mma.sync bf16x3 GEMM (unchanged from R6): 2-stage pipeline, 2 CTAs/SM.
// ---------------------------------------------------------------------------
#define STG_BYTES 40960
#define T_AHI 0
#define T_ALO 10240
#define T_BHI 20480
#define T_BLO 30720

template <int MODE>
__global__ __launch_bounds__(256, 2)
void gemm_bf16x3(const __nv_bfloat16* __restrict__ Ahi, const __nv_bfloat16* __restrict__ Alo,
                 const __nv_bfloat16* __restrict__ Bhi, const __nv_bfloat16* __restrict__ Blo,
                 const float* __restrict__ bias, float* __restrict__ C,
                 __nv_bfloat16* __restrict__ qhi, __nv_bfloat16* __restrict__ qlo,
                 __nv_bfloat16* __restrict__ khi, __nv_bfloat16* __restrict__ klo,
                 __nv_bfloat16* __restrict__ vhi, __nv_bfloat16* __restrict__ vlo,
                 int M, int N, int K)
{
    extern __shared__ char dynsm[];
    const uint32_t sb0 = smem_u32(dynsm);

    const int tid = threadIdx.x;
    const int wid = tid >> 5;
    const int l   = tid & 31;
    const int wm  = wid >> 1;
    const int wn  = wid & 1;
    const size_t m0 = (size_t)blockIdx.y * 128;
    const size_t n0 = (size_t)blockIdx.x * 128;

    const int r1 = tid >> 2;
    const int r2 = r1 + 64;
    const int cc = (tid & 3);
    const uint32_t sm_off1 = (uint32_t)r1 * 80 + cc * 16;
    const uint32_t sm_off2 = (uint32_t)r2 * 80 + cc * 16;

    const int nchunks = K >> 5;

    auto issue_stage = [&](int c, int buf) {
        const int kc = c << 5;
        const uint32_t sb = sb0 + buf * STG_BYTES;
        cp16(sb + T_AHI + sm_off1, Ahi + (m0 + r1) * K + kc + cc * 8);
        cp16(sb + T_AHI + sm_off2, Ahi + (m0 + r2) * K + kc + cc * 8);
        cp16(sb + T_ALO + sm_off1, Alo + (m0 + r1) * K + kc + cc * 8);
        cp16(sb + T_ALO + sm_off2, Alo + (m0 + r2) * K + kc + cc * 8);
        cp16(sb + T_BHI + sm_off1, Bhi + (n0 + r1) * K + kc + cc * 8);
        cp16(sb + T_BHI + sm_off2, Bhi + (n0 + r2) * K + kc + cc * 8);
        cp16(sb + T_BLO + sm_off1, Blo + (n0 + r1) * K + kc + cc * 8);
        cp16(sb + T_BLO + sm_off2, Blo + (n0 + r2) * K + kc + cc * 8);
        CP_COMMIT();
    };

    const int aRow = (l & 7) + ((l >> 3) & 1) * 8;
    const int aCol8 = (l >> 4) * 8;
    const int bRow = (l & 7) + ((l >> 4) & 1) * 8;
    const int bCol8 = ((l >> 3) & 1) * 8;

    float acc[2][8][4];
    #pragma unroll
    for (int mt = 0; mt < 2; mt++)
        #pragma unroll
        for (int nt = 0; nt < 8; nt++)
            #pragma unroll
            for (int k = 0; k < 4; k++) acc[mt][nt][k] = 0.f;

    issue_stage(0, 0);

    for (int c = 0; c < nchunks; c++) {
        if (c + 1 < nchunks) {
            issue_stage(c + 1, (c + 1) & 1);
            CP_WAIT1();
        } else {
            CP_WAIT0();
        }
        __syncthreads();

        const uint32_t sb = sb0 + (c & 1) * STG_BYTES;
        const uint32_t aBase = sb + (uint32_t)(wm * 32 + aRow) * 80 + aCol8 * 2;
        const uint32_t bBase = sb + (uint32_t)(wn * 64 + bRow) * 80 + bCol8 * 2;

        #pragma unroll
        for (int ks = 0; ks < 2; ks++) {
            uint32_t ah[2][4], al4[2][4];
            #pragma unroll
            for (int mt = 0; mt < 2; mt++) {
                ldsm4(ah[mt],  aBase + T_AHI + mt * (16 * 80) + ks * 32);
                ldsm4(al4[mt], aBase + T_ALO + mt * (16 * 80) + ks * 32);
            }
            #pragma unroll
            for (int np = 0; np < 4; np++) {
                uint32_t bh[4], bl4[4];
                ldsm4(bh,  bBase + T_BHI + np * (16 * 80) + ks * 32);
                ldsm4(bl4, bBase + T_BLO + np * (16 * 80) + ks * 32);
                #pragma unroll
                for (int mt = 0; mt < 2; mt++)
                    #pragma unroll
                    for (int sub = 0; sub < 2; sub++) {
                        const int nt = np * 2 + sub;
                        mma_bf16(acc[mt][nt], ah[mt],  &bh[sub * 2]);
                        mma_bf16(acc[mt][nt], ah[mt],  &bl4[sub * 2]);
                        mma_bf16(acc[mt][nt], al4[mt], &bh[sub * 2]);
                    }
            }
        }
        __syncthreads();
    }

    if (MODE == 0) {
        #pragma unroll
        for (int mt = 0; mt < 2; mt++) {
            const size_t row0 = m0 + wm * 32 + mt * 16 + (l >> 2);
            #pragma unroll
            for (int nt = 0; nt < 8; nt++) {
                const size_t col = n0 + wn * 64 + nt * 8 + (l & 3) * 2;
                const float b0 = bias[col], b1 = bias[col + 1];
                float2 v0 = { acc[mt][nt][0] + b0, acc[mt][nt][1] + b1 };
                float2 v1 = { acc[mt][nt][2] + b0, acc[mt][nt][3] + b1 };
                *reinterpret_cast<float2*>(&C[row0 * N + col]) = v0;
                *reinterpret_cast<float2*>(&C[(row0 + 8) * N + col]) = v1;
            }
        }
    } else {
        const int colbase = (int)n0 + wn * 64;
        const int sel = colbase >> 10;
        const int head = (colbase >> 6) & 15;
        __nv_bfloat16* dh = (sel == 0) ? qhi : (sel == 1) ? khi : vhi;
        __nv_bfloat16* dl = (sel == 0) ? qlo : (sel == 1) ? klo : vlo;
        #pragma unroll
        for (int mt = 0; mt < 2; mt++) {
            const int row0 = (int)m0 + wm * 32 + mt * 16 + (l >> 2);
            const int bb = row0 >> 11;
            const int t0 = row0 & 2047;
            const size_t base = ((size_t)(bb * NH + head) * NT + t0) * NHD;
            #pragma unroll
            for (int nt = 0; nt < 8; nt++) {
                const int col = colbase + nt * 8 + (l & 3) * 2;
                const int d = col & 63;
                const float b0 = bias[col], b1 = bias[col + 1];
                const float v0 = acc[mt][nt][0] + b0, v1 = acc[mt][nt][1] + b1;
                const float v2 = acc[mt][nt][2] + b0, v3 = acc[mt][nt][3] + b1;
                const uint32_t h0 = packbf(v0, v1), lo0 = packlo(v0, v1, h0);
                const uint32_t h1 = packbf(v2, v3), lo1 = packlo(v2, v3, h1);
                *reinterpret_cast<uint32_t*>(dh + base + d)            = h0;
                *reinterpret_cast<uint32_t*>(dl + base + d)            = lo0;
                *reinterpret_cast<uint32_t*>(dh + base + 8 * NHD + d)  = h1;
                *reinterpret_cast<uint32_t*>(dl + base + 8 * NHD + d)  = lo1;
            }
        }
    }
}

// ---------------------------------------------------------------------------
// Tensor-core flash attention, key tile 64, 2 CTAs/SM.
// Grid (16, H, B), 256 threads (8 warps x 16 q-rows).
// smem: 2 x 36864 KV (Khi|Klo|Vhi|Vlo @ 64 rows) + 18432 bias = 92160 B.
// Q (128 rows hi+lo) staged in buf1 before the loop.
// ---------------------------------------------------------------------------
#define FROWB 144
#define KVARR64 (64 * FROWB)          // 9216
#define KVBUF64 (4 * KVARR64)         // 36864 : Khi|Klo|Vhi|Vlo
#define QARR (128 * FROWB)            // 18432
#define OFF_BIAS64 (2 * KVBUF64)      // 73728
#define BIAS_STRB64 144               // 64 bf16 + 16B pad
#define FLASH_SMEM (OFF_BIAS64 + 128 * BIAS_STRB64)   // 92160

__global__ __launch_bounds__(256, 2)
void flash_mma(const __nv_bfloat16* __restrict__ qhi, const __nv_bfloat16* __restrict__ qlo,
               const __nv_bfloat16* __restrict__ khi, const __nv_bfloat16* __restrict__ klo,
               const __nv_bfloat16* __restrict__ vhi, const __nv_bfloat16* __restrict__ vlo,
               const __nv_bfloat16* __restrict__ ebias,
               __nv_bfloat16* __restrict__ out_hi, __nv_bfloat16* __restrict__ out_lo)
{
    extern __shared__ char sm[];
    const uint32_t s0 = smem_u32(sm);
    const int tid = threadIdx.x, w = tid >> 5, l = tid & 31;
    const int qb = 15 - blockIdx.x;          // heavy CTAs first
    const int h = blockIdx.y, b = blockIdx.z;
    const int q0 = qb * 128;
    const size_t hoff = (size_t)(b * NH + h) * NT * NHD;
    const int ntiles = 2 * qb + 2;           // key tiles of 64

    auto issue_kv = [&](int jt2, int bsel2) {
        #pragma unroll
        for (int i = 0; i < 8; i++) {
            const int ck = tid + i * 256;            // 0..2047
            const int arr = ck >> 9;                 // 0..3
            const int row = (ck >> 3) & 63;
            const int seg = ck & 7;
            const size_t go = hoff + (size_t)(jt2 * 64 + row) * NHD + seg * 8;
            const __nv_bfloat16* src = (arr == 0) ? khi + go : (arr == 1) ? klo + go
                                      : (arr == 2) ? vhi + go : vlo + go;
            cp16(s0 + bsel2 * KVBUF64 + arr * KVARR64 + row * FROWB + seg * 16, src);
        }
        CP_COMMIT();
    };
    auto issue_bias = [&](int jt2) {
        #pragma unroll
        for (int i = 0; i < 4; i++) {
            const int cb = tid + i * 256;            // 0..1023
            const int row = cb >> 3;                 // 0..127
            const int seg = cb & 7;
            const __nv_bfloat16* src =
                ebias + ((size_t)b * NT + q0 + row) * NT + jt2 * 64 + seg * 8;
            cp16(s0 + OFF_BIAS64 + row * BIAS_STRB64 + seg * 16, src);
        }
        CP_COMMIT();
    };

    // prologue: Q (128 rows hi+lo) -> buf1, KV(0) -> buf0, bias(0)
    #pragma unroll
    for (int i = 0; i < 8; i++) {
        const int cq = tid + i * 256;                // 0..2047
        const int arr = cq >> 10;                    // 0=hi,1=lo
        const int row = (cq >> 3) & 127;
        const int seg = cq & 7;
        const __nv_bfloat16* src = (arr ? qlo : qhi) + hoff + (size_t)(q0 + row) * NHD + seg * 8;
        cp16(s0 + KVBUF64 + arr * QARR + row * FROWB + seg * 16, src);
    }
    CP_COMMIT();
    issue_kv(0, 0);
    issue_bias(0);

    CP_WAIT2();                 // Q arrived
    __syncthreads();

    // Q fragments (A-operand, m16k16): 4 k-steps, hi+lo
    uint32_t qh[4][4], ql4[4][4];
    {
        const uint32_t rowOff = (uint32_t)(w * 16 + (l & 7) + ((l >> 3) & 1) * 8);
        const uint32_t colB = (uint32_t)((l >> 4) * 16);
        const uint32_t qbase = s0 + KVBUF64 + rowOff * FROWB + colB;
        #pragma unroll
        for (int ks = 0; ks < 4; ks++) {
            ldsm4(qh[ks],  qbase + ks * 32);
            ldsm4(ql4[ks], qbase + QARR + ks * 32);
        }
    }
    __syncthreads();            // all warps done with Q region (buf1)

    float O[8][4];
    #pragma unroll
    for (int nt = 0; nt < 8; nt++)
        #pragma unroll
        for (int k = 0; k < 4; k++) O[nt][k] = 0.f;
    float m0 = -INFINITY, m1 = -INFINITY, l0 = 0.f, l1 = 0.f;

    const int r0 = w * 16 + (l >> 2), r1 = r0 + 8;
    const int gq0 = q0 + r0, gq1 = q0 + r1;
    const uint32_t nRow = (uint32_t)((l & 7) + ((l >> 4) & 1) * 8);
    const uint32_t kColB = (uint32_t)(((l >> 3) & 1) * 16);
    const uint32_t vRowP = (uint32_t)((l & 7) + ((l >> 3) & 1) * 8);
    const uint32_t vColB = (uint32_t)(((l >> 4) & 1) * 16);

    for (int jt = 0; jt < ntiles; jt++) {
        const int bsel = jt & 1;
        CP_WAIT0();
        __syncthreads();
        if (jt + 1 < ntiles) issue_kv(jt + 1, bsel ^ 1);

        // ---- S = Q K^T (bf16x3) over 64 keys
        float acc[8][4];
        #pragma unroll
        for (int nt = 0; nt < 8; nt++)
            #pragma unroll
            for (int k = 0; k < 4; k++) acc[nt][k] = 0.f;

        const uint32_t kb = s0 + bsel * KVBUF64;
        #pragma unroll
        for (int ks = 0; ks < 4; ks++) {
            #pragma unroll
            for (int np = 0; np < 4; np++) {
                uint32_t khf[4], klf[4];
                const uint32_t a = kb + (np * 16 + nRow) * FROWB + kColB + ks * 32;
                ldsm4(khf, a);
                ldsm4(klf, a + KVARR64);
                #pragma unroll
                for (int sub = 0; sub < 2; sub++) {
                    const int nt = np * 2 + sub;
                    mma_bf16(acc[nt], qh[ks],  &khf[sub * 2]);
                    mma_bf16(acc[nt], qh[ks],  &klf[sub * 2]);
                    mma_bf16(acc[nt], ql4[ks], &khf[sub * 2]);
                }
            }
        }

        // ---- scale + bias (bf16) + causal mask + online softmax
        float mx0 = -INFINITY, mx1 = -INFINITY;
        const bool masktile = (jt >= 2 * qb);       // last two tiles touch diagonal
        const uint32_t biasOff = (uint32_t)(OFF_BIAS64 + (l & 3) * 4);
        #pragma unroll
        for (int nt = 0; nt < 8; nt++) {
            const char* bp = sm + biasOff + (uint32_t)r0 * BIAS_STRB64 + nt * 16;
            float2 bv0 = __bfloat1622float2(*reinterpret_cast<const __nv_bfloat162*>(bp));
            float2 bv1 = __bfloat1622float2(
                *reinterpret_cast<const __nv_bfloat162*>(bp + 8 * BIAS_STRB64));
            float v0 = acc[nt][0] * 0.125f + bv0.x;
            float v1 = acc[nt][1] * 0.125f + bv0.y;
            float v2 = acc[nt][2] * 0.125f + bv1.x;
            float v3 = acc[nt][3] * 0.125f + bv1.y;
            if (masktile) {
                const int kc = jt * 64 + nt * 8 + 2 * (l & 3);
                if (kc > gq0)     v0 = -1e30f;
                if (kc + 1 > gq0) v1 = -1e30f;
                if (kc > gq1)     v2 = -1e30f;
                if (kc + 1 > gq1) v3 = -1e30f;
            }
            acc[nt][0] = v0; acc[nt][1] = v1; acc[nt][2] = v2; acc[nt][3] = v3;
            mx0 = fmaxf(mx0, fmaxf(v0, v1));
            mx1 = fmaxf(mx1, fmaxf(v2, v3));
        }
        mx0 = fmaxf(mx0, __shfl_xor_sync(0xffffffff, mx0, 1));
        mx0 = fmaxf(mx0, __shfl_xor_sync(0xffffffff, mx0, 2));
        mx1 = fmaxf(mx1, __shfl_xor_sync(0xffffffff, mx1, 1));
        mx1 = fmaxf(mx1, __shfl_xor_sync(0xffffffff, mx1, 2));

        const float mn0 = fmaxf(m0, mx0), mn1 = fmaxf(m1, mx1);
        const float c0 = __expf(m0 - mn0), c1 = __expf(m1 - mn1);
        float rs0 = 0.f, rs1 = 0.f;
        #pragma unroll
        for (int nt = 0; nt < 8; nt++) {
            const float p0 = __expf(acc[nt][0] - mn0);
            const float p1 = __expf(acc[nt][1] - mn0);
            const float p2 = __expf(acc[nt][2] - mn1);
            const float p3 = __expf(acc[nt][3] - mn1);
            acc[nt][0] = p0; acc[nt][1] = p1; acc[nt][2] = p2; acc[nt][3] = p3;
            rs0 += p0 + p1;
            rs1 += p2 + p3;
        }
        rs0 += __shfl_xor_sync(0xffffffff, rs0, 1);
        rs0 += __shfl_xor_sync(0xffffffff, rs0, 2);
        rs1 += __shfl_xor_sync(0xffffffff, rs1, 1);
        rs1 += __shfl_xor_sync(0xffffffff, rs1, 2);
        l0 = l0 * c0 + rs0;
        l1 = l1 * c1 + rs1;
        m0 = mn0; m1 = mn1;
        #pragma unroll
        for (int nt = 0; nt < 8; nt++) {
            O[nt][0] *= c0; O[nt][1] *= c0; O[nt][2] *= c1; O[nt][3] *= c1;
        }

        __syncthreads();                       // bias tile consumed by all warps
        if (jt + 1 < ntiles) issue_bias(jt + 1);

        // ---- O += P V (bf16x3) over 64 keys
        const uint32_t vb = kb + 2 * KVARR64;
        #pragma unroll
        for (int kk = 0; kk < 4; kk++) {
            uint32_t phi[4], plo[4];
            phi[0] = packbf(acc[2 * kk][0], acc[2 * kk][1]);
            plo[0] = packlo(acc[2 * kk][0], acc[2 * kk][1], phi[0]);
            phi[1] = packbf(acc[2 * kk][2], acc[2 * kk][3]);
            plo[1] = packlo(acc[2 * kk][2], acc[2 * kk][3], phi[1]);
            phi[2] = packbf(acc[2 * kk + 1][0], acc[2 * kk + 1][1]);
            plo[2] = packlo(acc[2 * kk + 1][0], acc[2 * kk + 1][1], phi[2]);
            phi[3] = packbf(acc[2 * kk + 1][2], acc[2 * kk + 1][3]);
            plo[3] = packlo(acc[2 * kk + 1][2], acc[2 * kk + 1][3], phi[3]);
            #pragma unroll
            for (int nn = 0; nn < 4; nn++) {
                uint32_t vhf[4], vlf[4];
                const uint32_t va = vb + (kk * 16 + vRowP) * FROWB + nn * 32 + vColB;
                ldsm4t(vhf, va);
                ldsm4t(vlf, va + KVARR64);
                #pragma unroll
                for (int sub = 0; sub < 2; sub++) {
                    const int nt = nn * 2 + sub;
                    mma_bf16(O[nt], phi, &vhf[sub * 2]);
                    mma_bf16(O[nt], phi, &vlf[sub * 2]);
                    mma_bf16(O[nt], plo, &vhf[sub * 2]);
                }
            }
        }
    }

    // ---- epilogue: O/l -> bf16 hi/lo, [B,T,D] layout
    const float inv0 = 1.f / l0, inv1 = 1.f / l1;
    const size_t a0 = ((size_t)b * NT + gq0) * ND + h * NHD + 2 * (l & 3);
    const size_t a1 = ((size_t)b * NT + gq1) * ND + h * NHD + 2 * (l & 3);
    #pragma unroll
    for (int nt = 0; nt < 8; nt++) {
        const float o0 = O[nt][0] * inv0, o1 = O[nt][1] * inv0;
        const float o2 = O[nt][2] * inv1, o3 = O[nt][3] * inv1;
        const uint32_t h0 = packbf(o0, o1), lo0 = packlo(o0, o1, h0);
        const uint32_t h1 = packbf(o2, o3), lo1 = packlo(o2, o3, h1);
        *reinterpret_cast<uint32_t*>(out_hi + a0 + nt * 8) = h0;
        *reinterpret_cast<uint32_t*>(out_lo + a0 + nt * 8) = lo0;
        *reinterpret_cast<uint32_t*>(out_hi + a1 + nt * 8) = h1;
        *reinterpret_cast<uint32_t*>(out_lo + a1 + nt * 8) = lo1;
    }
}

// ---------------------------------------------------------------------------
extern "C" void kernel_launch(void* const* d_in, const int* in_sizes, int n_in,
                              void* d_out, int out_size)
{
    const float* x     = (const float*)d_in[0];
    const float* eb    = (const float*)d_in[1];
    const float* Wqkv  = (const float*)d_in[2];
    const float* bqkv  = (const float*)d_in[3];
    const float* Wout  = (const float*)d_in[4];
    const float* bout  = (const float*)d_in[5];
    float* out = (float*)d_out;

    __nv_bfloat16 *xhi, *xlo, *wqhi, *wqlo, *wohi, *wolo, *athi, *atlo;
    __nv_bfloat16 *qhi, *qlo, *khi2, *klo2, *vhi2, *vlo2, *ebbf;
    cudaGetSymbolAddress((void**)&xhi,  g_x_hi);
    cudaGetSymbolAddress((void**)&xlo,  g_x_lo);
    cudaGetSymbolAddress((void**)&wqhi, g_wq_hi);
    cudaGetSymbolAddress((void**)&wqlo, g_wq_lo);
    cudaGetSymbolAddress((void**)&wohi, g_wo_hi);
    cudaGetSymbolAddress((void**)&wolo, g_wo_lo);
    cudaGetSymbolAddress((void**)&athi, g_att_hi);
    cudaGetSymbolAddress((void**)&atlo, g_att_lo);
    cudaGetSymbolAddress((void**)&qhi,  g_q_hi);
    cudaGetSymbolAddress((void**)&qlo,  g_q_lo);
    cudaGetSymbolAddress((void**)&khi2, g_k_hi);
    cudaGetSymbolAddress((void**)&klo2, g_k_lo);
    cudaGetSymbolAddress((void**)&vhi2, g_v_hi);
    cudaGetSymbolAddress((void**)&vlo2, g_v_lo);
    cudaGetSymbolAddress((void**)&ebbf, g_eb_bf);

    const int M = NB * NT;   // 8192

    // 0) prepasses
    split_kernel<<<(M * ND + 255) / 256, 256>>>(x, xhi, xlo, M * ND);
    {
        dim3 blk(32, 8);
        transpose_split_kernel<<<dim3(3 * ND / 32, ND / 32), blk>>>(Wqkv, wqhi, wqlo, ND, 3 * ND);
        transpose_split_kernel<<<dim3(ND / 32, ND / 32), blk>>>(Wout, wohi, wolo, ND, ND);
    }
    bias_to_bf16_kernel<<<(int)(((size_t)NB * NT * NT) / 4 / 256), 256>>>(eb, ebbf);

    const int gemm_smem = 2 * STG_BYTES;   // 81920 -> 2 CTAs/SM
    cudaFuncSetAttribute(gemm_bf16x3<0>, cudaFuncAttributeMaxDynamicSharedMemorySize, gemm_smem);
    cudaFuncSetAttribute(gemm_bf16x3<1>, cudaFuncAttributeMaxDynamicSharedMemorySize, gemm_smem);

    // 1) QKV projection, fused per-head split epilogue
    gemm_bf16x3<1><<<dim3(3 * ND / 128, M / 128), 256, gemm_smem>>>(
        xhi, xlo, wqhi, wqlo, bqkv, nullptr,
        qhi, qlo, khi2, klo2, vhi2, vlo2, M, 3 * ND, ND);

    // 2) tensor-core flash attention (2 CTAs/SM)
    cudaFuncSetAttribute(flash_mma, cudaFuncAttributeMaxDynamicSharedMemorySize, FLASH_SMEM);
    flash_mma<<<dim3(NT / 128, NH, NB), 256, FLASH_SMEM>>>(
        qhi, qlo, khi2, klo2, vhi2, vlo2, ebbf, athi, atlo);

    // 3) output projection (fp32 out + bias)
    gemm_bf16x3<0><<<dim3(ND / 128, M / 128), 256, gemm_smem>>>(
        athi, atlo, wohi, wolo, bout, out,
        nullptr, nullptr, nullptr, nullptr, nullptr, nullptr, M, ND, ND);
}